// round 7
// baseline (speedup 1.0000x reference)
#include <cuda_runtime.h>
#include <math.h>

#define NN    100000
#define EE    3200000
#define NFEAT 256
#define NHID  128
#define NCLASS 40

// ---------------- scratch ----------------
__device__ __align__(16) float g_s1[NN * NHID];     // x @ W1 (51.2 MB)
__device__ __align__(16) float g_h [NN * NHID];     // relu(A@s1 + b1) (51.2 MB)
__device__ __align__(16) float g_s2[NN * NCLASS];   // h @ W2 (16 MB)
__device__ int g_rowptr[NN + 1];

// ---------------- f32x2 packed helpers ----------------
__device__ __forceinline__ unsigned long long ffma2(unsigned long long a,
                                                    unsigned long long b,
                                                    unsigned long long c) {
    unsigned long long d;
    asm("fma.rn.f32x2 %0, %1, %2, %3;" : "=l"(d) : "l"(a), "l"(b), "l"(c));
    return d;
}
__device__ __forceinline__ unsigned long long dup2(float a) {
    unsigned long long d;
    asm("mov.b64 %0, {%1, %1};" : "=l"(d) : "f"(a));
    return d;
}
__device__ __forceinline__ float2 unpack2(unsigned long long v) {
    float2 f;
    asm("mov.b64 {%0, %1}, %2;" : "=f"(f.x), "=f"(f.y) : "l"(v));
    return f;
}
__device__ __forceinline__ unsigned long long ldg64cg(const void* p) {
    unsigned long long v;
    asm volatile("ld.global.cg.b64 %0, [%1];" : "=l"(v) : "l"(p));
    return v;
}
__device__ __forceinline__ void ldg128cg(const void* p, unsigned long long& a,
                                         unsigned long long& b) {
    asm volatile("ld.global.cg.v2.u64 {%0, %1}, [%2];" : "=l"(a), "=l"(b) : "l"(p));
}

// ---------------- cp.async helpers ----------------
__device__ __forceinline__ void cpa16(unsigned dst, const void* src, bool pred) {
    int sz = pred ? 16 : 0;
    asm volatile("cp.async.ca.shared.global [%0], [%1], 16, %2;\n"
                 :: "r"(dst), "l"(src), "r"(sz));
}
__device__ __forceinline__ void cpa_commit() { asm volatile("cp.async.commit_group;\n"); }
__device__ __forceinline__ void cpa_wait3()  { asm volatile("cp.async.wait_group 3;\n"); }
__device__ __forceinline__ void cpa_wait2()  { asm volatile("cp.async.wait_group 2;\n"); }
__device__ __forceinline__ void cpa_wait1()  { asm volatile("cp.async.wait_group 1;\n"); }
__device__ __forceinline__ void cpa_wait0()  { asm volatile("cp.async.wait_group 0;\n"); }

// ---------------- CSR row_ptr ----------------
__global__ void build_rowptr_kernel(const int* __restrict__ arow) {
    int r = blockIdx.x * blockDim.x + threadIdx.x;
    if (r > NN) return;
    int lo = 0, hi = EE;
    while (lo < hi) {
        int mid = (lo + hi) >> 1;
        if (arow[mid] < r) lo = mid + 1; else hi = mid;
    }
    g_rowptr[r] = lo;
}

// ---------------- GEMM1: g_s1 = X @ W1, 128x128 tile, f32x2, cp.async 2-stage ----------------
#define G1_BM 128
#define G1_BK 16
#define G1_AS 20
#define G1_NT (NFEAT / G1_BK)
__global__ void __launch_bounds__(256) gemm1_kernel(const float* __restrict__ X,
                                                    const float* __restrict__ W1) {
    __shared__ float As[2][G1_BM * G1_AS];
    __shared__ float Bs[2][G1_BK * NHID];

    const int tid = threadIdx.x;
    const int tx  = tid & 15;
    const int ty  = tid >> 4;
    const int row0 = blockIdx.x * G1_BM;

    unsigned long long acc[8][4];
#pragma unroll
    for (int i = 0; i < 8; i++)
#pragma unroll
        for (int j = 0; j < 4; j++) acc[i][j] = 0ull;

    unsigned asb = (unsigned)__cvta_generic_to_shared(&As[0][0]);
    unsigned bsb = (unsigned)__cvta_generic_to_shared(&Bs[0][0]);

#define G1_PREFETCH(stage, k0)                                                     \
    do {                                                                           \
        _Pragma("unroll")                                                          \
        for (int j = 0; j < 2; j++) {                                              \
            int fi = j * 256 + tid;                                                \
            int r  = fi >> 2;                                                      \
            int c4 = (fi & 3) * 4;                                                 \
            int grow = row0 + r;                                                   \
            unsigned dst = asb + (stage) * (G1_BM * G1_AS * 4) + (r * G1_AS + c4) * 4; \
            cpa16(dst, &X[(size_t)grow * NFEAT + (k0) + c4], grow < NN);           \
        }                                                                          \
        _Pragma("unroll")                                                          \
        for (int j = 0; j < 2; j++) {                                              \
            int fi = j * 256 + tid;                                                \
            int r  = fi >> 5;                                                      \
            int c  = (fi & 31) * 4;                                                \
            unsigned dst = bsb + (stage) * (G1_BK * NHID * 4) + (r * NHID + c) * 4;\
            cpa16(dst, &W1[(size_t)((k0) + r) * NHID + c], true);                  \
        }                                                                          \
        cpa_commit();                                                              \
    } while (0)

    G1_PREFETCH(0, 0);

    for (int t = 0; t < G1_NT; t++) {
        if (t + 1 < G1_NT) {
            G1_PREFETCH((t + 1) & 1, (t + 1) * G1_BK);
            cpa_wait1();
        } else {
            cpa_wait0();
        }
        __syncthreads();

        const int st = t & 1;
#pragma unroll
        for (int kk = 0; kk < G1_BK; kk++) {
            unsigned long long ad[8];
#pragma unroll
            for (int i = 0; i < 8; i++)
                ad[i] = dup2(As[st][(ty * 8 + i) * G1_AS + kk]);
            unsigned long long bp[4];
#pragma unroll
            for (int j = 0; j < 4; j++)
                bp[j] = *(const unsigned long long*)&Bs[st][kk * NHID + 2 * tx + 32 * j];
#pragma unroll
            for (int i = 0; i < 8; i++)
#pragma unroll
                for (int j = 0; j < 4; j++)
                    acc[i][j] = ffma2(ad[i], bp[j], acc[i][j]);
        }
        __syncthreads();
    }

#pragma unroll
    for (int i = 0; i < 8; i++) {
        int grow = row0 + ty * 8 + i;
        if (grow < NN) {
#pragma unroll
            for (int j = 0; j < 4; j++) {
                float2 v = unpack2(acc[i][j]);
                *(float2*)&g_s1[(size_t)grow * NHID + 2 * tx + 32 * j] = v;
            }
        }
    }
#undef G1_PREFETCH
}

// ---------------- SpMM1 + bias + ReLU (warp/row, f32x2 accum, 16B gathers) ----------------
__global__ void spmm1_kernel(const int* __restrict__ acol, const float* __restrict__ aval,
                             const float* __restrict__ b1) {
    int warp = (blockIdx.x * blockDim.x + threadIdx.x) >> 5;
    int lane = threadIdx.x & 31;
    if (warp >= NN) return;

    int s = g_rowptr[warp];
    int e = g_rowptr[warp + 1];

    const char* S1b = (const char*)g_s1 + (size_t)lane * 16;
    unsigned long long a01 = 0ull, a23 = 0ull;

    int i = s;
    if ((i & 1) && i < e) {
        int   c = __ldcs(&acol[i]);
        float v = __ldcs(&aval[i]);
        unsigned long long d0, d1;
        ldg128cg(S1b + (size_t)c * 512, d0, d1);
        unsigned long long vv = dup2(v);
        a01 = ffma2(vv, d0, a01);
        a23 = ffma2(vv, d1, a23);
        i++;
    }
    for (; i + 1 < e; i += 2) {
        int2   c2 = __ldcs((const int2*)&acol[i]);
        float2 v2 = __ldcs((const float2*)&aval[i]);
        unsigned long long d0, d1, e0, e1;
        ldg128cg(S1b + (size_t)c2.x * 512, d0, d1);
        ldg128cg(S1b + (size_t)c2.y * 512, e0, e1);
        unsigned long long vx = dup2(v2.x), vy = dup2(v2.y);
        a01 = ffma2(vx, d0, a01);
        a23 = ffma2(vx, d1, a23);
        a01 = ffma2(vy, e0, a01);
        a23 = ffma2(vy, e1, a23);
    }
    if (i < e) {
        int   c = __ldcs(&acol[i]);
        float v = __ldcs(&aval[i]);
        unsigned long long d0, d1;
        ldg128cg(S1b + (size_t)c * 512, d0, d1);
        unsigned long long vv = dup2(v);
        a01 = ffma2(vv, d0, a01);
        a23 = ffma2(vv, d1, a23);
    }

    float2 p01 = unpack2(a01), p23 = unpack2(a23);
    float4 b = ((const float4*)b1)[lane];
    float4 r;
    r.x = fmaxf(p01.x + b.x, 0.f);
    r.y = fmaxf(p01.y + b.y, 0.f);
    r.z = fmaxf(p23.x + b.z, 0.f);
    r.w = fmaxf(p23.y + b.w, 0.f);
    ((float4*)g_h)[(size_t)warp * 32 + lane] = r;
}

// ---------------- GEMM2: s2 = h @ W2 ----------------
// BM=128, 128 threads, thread tile 4 rows (stride 32) x 5 col-pairs (f32x2).
// 4-stage cp.async pipeline on Hs (BK=8, row stride 12 floats = 48B, cp.async-legal,
// conflict-free). Wp = W2 pre-paired in smem. 44KB static smem -> 5 blocks/SM.
#define G2_BM 128
#define G2_BK 8
#define G2_HS 12
#define G2_NT (NHID / G2_BK)     // 16
__global__ void __launch_bounds__(128) gemm2_kernel(const float* __restrict__ W2) {
    __shared__ float  Hs[4][G2_BM * G2_HS];   // 4 x 6144 B
    __shared__ float2 Wp[NHID * 20];          // 20480 B

    const int tid = threadIdx.x;
    const int pg  = tid & 3;                  // pairs pg*5 .. pg*5+4
    const int rg  = tid >> 2;                 // rows rg + 32*i, i=0..3
    const int row0 = blockIdx.x * G2_BM;

    for (int j = tid; j < NHID * 20; j += 128) {
        int k = j / 20, p = j % 20;
        Wp[j] = *(const float2*)&W2[k * NCLASS + 2 * p];
    }

    unsigned hsb = (unsigned)__cvta_generic_to_shared(&Hs[0][0]);

    // per k-tile: 128 rows x 8 floats = 256 float4, 2 per thread
#define G2_PREFETCH(tt)                                                            \
    do {                                                                           \
        int stage_ = (tt) & 3;                                                     \
        int k0_ = (tt) * G2_BK;                                                    \
        _Pragma("unroll")                                                          \
        for (int j = 0; j < 2; j++) {                                              \
            int fi = j * 128 + tid;          /* [0,256) float4 */                  \
            int r  = fi >> 1;                /* 2 float4 per 8-float row */        \
            int c4 = (fi & 1) * 4;                                                 \
            int grow = row0 + r;                                                   \
            unsigned dst = hsb + stage_ * (G2_BM * G2_HS * 4) + (r * G2_HS + c4) * 4; \
            cpa16(dst, &g_h[(size_t)grow * NHID + k0_ + c4], grow < NN);           \
        }                                                                          \
        cpa_commit();                                                              \
    } while (0)

    G2_PREFETCH(0);
    G2_PREFETCH(1);
    G2_PREFETCH(2);

    unsigned long long acc[4][5];
#pragma unroll
    for (int i = 0; i < 4; i++)
#pragma unroll
        for (int j = 0; j < 5; j++) acc[i][j] = 0ull;

    for (int t = 0; t < G2_NT; t++) {
        if (t + 3 < G2_NT) {
            G2_PREFETCH(t + 3);
            cpa_wait3();
        } else if (t + 2 < G2_NT) {
            cpa_wait2();
        } else if (t + 1 < G2_NT) {
            cpa_wait1();
        } else {
            cpa_wait0();
        }
        __syncthreads();

        const int st = t & 3;
        const int kbase = t * G2_BK;
#pragma unroll
        for (int kk = 0; kk < G2_BK; kk++) {
            unsigned long long hd[4];
#pragma unroll
            for (int i = 0; i < 4; i++)
                hd[i] = dup2(Hs[st][(rg + 32 * i) * G2_HS + kk]);
            unsigned long long wv[5];
#pragma unroll
            for (int j = 0; j < 5; j++)
                wv[j] = *(const unsigned long long*)&Wp[(kbase + kk) * 20 + pg * 5 + j];
#pragma unroll
            for (int i = 0; i < 4; i++)
#pragma unroll
                for (int j = 0; j < 5; j++)
                    acc[i][j] = ffma2(hd[i], wv[j], acc[i][j]);
        }
        __syncthreads();
    }

#pragma unroll
    for (int i = 0; i < 4; i++) {
        int grow = row0 + rg + 32 * i;
        if (grow < NN) {
#pragma unroll
            for (int j = 0; j < 5; j++) {
                float2 v = unpack2(acc[i][j]);
                *(float2*)&g_s2[(size_t)grow * NCLASS + 2 * (pg * 5 + j)] = v;
            }
        }
    }
#undef G2_PREFETCH
}

// ---------------- SpMM2 + bias + log_softmax (f32x2, 8-edge unroll, dual acc) ----------------
__global__ void spmm2_lsm_kernel(const int* __restrict__ acol, const float* __restrict__ aval,
                                 const float* __restrict__ b2, float* __restrict__ out) {
    int warp = (blockIdx.x * blockDim.x + threadIdx.x) >> 5;
    int lane = threadIdx.x & 31;
    if (warp >= NN) return;

    int s = g_rowptr[warp];
    int e = g_rowptr[warp + 1];
    bool active = lane < 20;

    const char* S2b = (const char*)g_s2 + (size_t)lane * 8;
    unsigned long long acc0 = 0ull, acc1 = 0ull;

    int i = s;
    while (i < e && (i & 3)) {
        int   c = __ldcs(&acol[i]);
        float v = __ldcs(&aval[i]);
        if (active) acc0 = ffma2(dup2(v), ldg64cg(S2b + (size_t)c * 160), acc0);
        i++;
    }
    for (; i + 7 < e; i += 8) {
        int4   ca = __ldcs((const int4*)&acol[i]);
        int4   cb = __ldcs((const int4*)&acol[i + 4]);
        float4 va = __ldcs((const float4*)&aval[i]);
        float4 vb = __ldcs((const float4*)&aval[i + 4]);
        if (active) {
            unsigned long long d0 = ldg64cg(S2b + (size_t)ca.x * 160);
            unsigned long long d1 = ldg64cg(S2b + (size_t)ca.y * 160);
            unsigned long long d2 = ldg64cg(S2b + (size_t)ca.z * 160);
            unsigned long long d3 = ldg64cg(S2b + (size_t)ca.w * 160);
            unsigned long long d4 = ldg64cg(S2b + (size_t)cb.x * 160);
            unsigned long long d5 = ldg64cg(S2b + (size_t)cb.y * 160);
            unsigned long long d6 = ldg64cg(S2b + (size_t)cb.z * 160);
            unsigned long long d7 = ldg64cg(S2b + (size_t)cb.w * 160);
            acc0 = ffma2(dup2(va.x), d0, acc0);
            acc1 = ffma2(dup2(va.y), d1, acc1);
            acc0 = ffma2(dup2(va.z), d2, acc0);
            acc1 = ffma2(dup2(va.w), d3, acc1);
            acc0 = ffma2(dup2(vb.x), d4, acc0);
            acc1 = ffma2(dup2(vb.y), d5, acc1);
            acc0 = ffma2(dup2(vb.z), d6, acc0);
            acc1 = ffma2(dup2(vb.w), d7, acc1);
        }
    }
    for (; i + 3 < e; i += 4) {
        int4   c4 = __ldcs((const int4*)&acol[i]);
        float4 v4 = __ldcs((const float4*)&aval[i]);
        if (active) {
            unsigned long long d0 = ldg64cg(S2b + (size_t)c4.x * 160);
            unsigned long long d1 = ldg64cg(S2b + (size_t)c4.y * 160);
            unsigned long long d2 = ldg64cg(S2b + (size_t)c4.z * 160);
            unsigned long long d3 = ldg64cg(S2b + (size_t)c4.w * 160);
            acc0 = ffma2(dup2(v4.x), d0, acc0);
            acc1 = ffma2(dup2(v4.y), d1, acc1);
            acc0 = ffma2(dup2(v4.z), d2, acc0);
            acc1 = ffma2(dup2(v4.w), d3, acc1);
        }
    }
    for (; i < e; i++) {
        int   c = __ldcs(&acol[i]);
        float v = __ldcs(&aval[i]);
        if (active) acc0 = ffma2(dup2(v), ldg64cg(S2b + (size_t)c * 160), acc0);
    }

    float2 a0 = unpack2(acc0), a1 = unpack2(acc1);
    float2 av = make_float2(a0.x + a1.x, a0.y + a1.y);
    if (active) {
        float2 bb = *(const float2*)&b2[2 * lane];
        av.x += bb.x;
        av.y += bb.y;
    }

    float m = active ? fmaxf(av.x, av.y) : -INFINITY;
#pragma unroll
    for (int off = 16; off > 0; off >>= 1)
        m = fmaxf(m, __shfl_xor_sync(0xFFFFFFFFu, m, off));

    float se = active ? (expf(av.x - m) + expf(av.y - m)) : 0.f;
#pragma unroll
    for (int off = 16; off > 0; off >>= 1)
        se += __shfl_xor_sync(0xFFFFFFFFu, se, off);

    float lse = m + logf(se);
    if (active) {
        out[(size_t)warp * NCLASS + 2 * lane]     = av.x - lse;
        out[(size_t)warp * NCLASS + 2 * lane + 1] = av.y - lse;
    }
}

// ---------------- launch ----------------
extern "C" void kernel_launch(void* const* d_in, const int* in_sizes, int n_in,
                              void* d_out, int out_size) {
    const float* x    = (const float*)d_in[0];
    const int*   arow = (const int*)  d_in[1];
    const int*   acol = (const int*)  d_in[2];
    const float* aval = (const float*)d_in[3];
    // d_in[4] = i (unused)
    const float* W1 = (const float*)d_in[5];
    const float* b1 = (const float*)d_in[6];
    const float* W2 = (const float*)d_in[7];
    const float* b2 = (const float*)d_in[8];
    float* out = (float*)d_out;

    build_rowptr_kernel<<<(NN + 1 + 255) / 256, 256>>>(arow);
    gemm1_kernel<<<(NN + G1_BM - 1) / G1_BM, 256>>>(x, W1);
    spmm1_kernel<<<(NN * 32 + 255) / 256, 256>>>(acol, aval, b1);
    gemm2_kernel<<<(NN + G2_BM - 1) / G2_BM, 128>>>(W2);
    spmm2_lsm_kernel<<<(NN * 32 + 255) / 256, 256>>>(acol, aval, b2, out);
}

// round 8
// speedup vs baseline: 1.0574x; 1.0574x over previous
#include <cuda_runtime.h>
#include <math.h>

#define NN    100000
#define EE    3200000
#define NFEAT 256
#define NHID  128
#define NCLASS 40

// ---------------- scratch ----------------
__device__ __align__(16) float g_s1[NN * NHID];     // x @ W1 (51.2 MB)
__device__ __align__(16) float g_h [NN * NHID];     // relu(A@s1 + b1) (51.2 MB)
__device__ __align__(16) float g_s2[NN * NCLASS];   // h @ W2 (16 MB)
__device__ int g_rowptr[NN + 1];

// ---------------- f32x2 packed helpers ----------------
__device__ __forceinline__ unsigned long long ffma2(unsigned long long a,
                                                    unsigned long long b,
                                                    unsigned long long c) {
    unsigned long long d;
    asm("fma.rn.f32x2 %0, %1, %2, %3;" : "=l"(d) : "l"(a), "l"(b), "l"(c));
    return d;
}
__device__ __forceinline__ unsigned long long dup2(float a) {
    unsigned long long d;
    asm("mov.b64 %0, {%1, %1};" : "=l"(d) : "f"(a));
    return d;
}
__device__ __forceinline__ float2 unpack2(unsigned long long v) {
    float2 f;
    asm("mov.b64 {%0, %1}, %2;" : "=f"(f.x), "=f"(f.y) : "l"(v));
    return f;
}
__device__ __forceinline__ unsigned long long ldg64cg(const void* p) {
    unsigned long long v;
    asm volatile("ld.global.cg.b64 %0, [%1];" : "=l"(v) : "l"(p));
    return v;
}
__device__ __forceinline__ void ldg128cg(const void* p, unsigned long long& a,
                                         unsigned long long& b) {
    asm volatile("ld.global.cg.v2.u64 {%0, %1}, [%2];" : "=l"(a), "=l"(b) : "l"(p));
}

// ---------------- cp.async helpers ----------------
__device__ __forceinline__ void cpa16(unsigned dst, const void* src, bool pred) {
    int sz = pred ? 16 : 0;
    asm volatile("cp.async.ca.shared.global [%0], [%1], 16, %2;\n"
                 :: "r"(dst), "l"(src), "r"(sz));
}
__device__ __forceinline__ void cpa_commit() { asm volatile("cp.async.commit_group;\n"); }
__device__ __forceinline__ void cpa_wait1()  { asm volatile("cp.async.wait_group 1;\n"); }
__device__ __forceinline__ void cpa_wait0()  { asm volatile("cp.async.wait_group 0;\n"); }

// ---------------- CSR row_ptr ----------------
__global__ void build_rowptr_kernel(const int* __restrict__ arow) {
    int r = blockIdx.x * blockDim.x + threadIdx.x;
    if (r > NN) return;
    int lo = 0, hi = EE;
    while (lo < hi) {
        int mid = (lo + hi) >> 1;
        if (arow[mid] < r) lo = mid + 1; else hi = mid;
    }
    g_rowptr[r] = lo;
}

// ---------------- GEMM1: g_s1 = X @ W1, 128x128 tile, f32x2, cp.async 2-stage ----------------
#define G1_BM 128
#define G1_BK 16
#define G1_AS 20
#define G1_NT (NFEAT / G1_BK)
__global__ void __launch_bounds__(256) gemm1_kernel(const float* __restrict__ X,
                                                    const float* __restrict__ W1) {
    __shared__ float As[2][G1_BM * G1_AS];
    __shared__ float Bs[2][G1_BK * NHID];

    const int tid = threadIdx.x;
    const int tx  = tid & 15;
    const int ty  = tid >> 4;
    const int row0 = blockIdx.x * G1_BM;

    unsigned long long acc[8][4];
#pragma unroll
    for (int i = 0; i < 8; i++)
#pragma unroll
        for (int j = 0; j < 4; j++) acc[i][j] = 0ull;

    unsigned asb = (unsigned)__cvta_generic_to_shared(&As[0][0]);
    unsigned bsb = (unsigned)__cvta_generic_to_shared(&Bs[0][0]);

#define G1_PREFETCH(stage, k0)                                                     \
    do {                                                                           \
        _Pragma("unroll")                                                          \
        for (int j = 0; j < 2; j++) {                                              \
            int fi = j * 256 + tid;                                                \
            int r  = fi >> 2;                                                      \
            int c4 = (fi & 3) * 4;                                                 \
            int grow = row0 + r;                                                   \
            unsigned dst = asb + (stage) * (G1_BM * G1_AS * 4) + (r * G1_AS + c4) * 4; \
            cpa16(dst, &X[(size_t)grow * NFEAT + (k0) + c4], grow < NN);           \
        }                                                                          \
        _Pragma("unroll")                                                          \
        for (int j = 0; j < 2; j++) {                                              \
            int fi = j * 256 + tid;                                                \
            int r  = fi >> 5;                                                      \
            int c  = (fi & 31) * 4;                                                \
            unsigned dst = bsb + (stage) * (G1_BK * NHID * 4) + (r * NHID + c) * 4;\
            cpa16(dst, &W1[(size_t)((k0) + r) * NHID + c], true);                  \
        }                                                                          \
        cpa_commit();                                                              \
    } while (0)

    G1_PREFETCH(0, 0);

    for (int t = 0; t < G1_NT; t++) {
        if (t + 1 < G1_NT) {
            G1_PREFETCH((t + 1) & 1, (t + 1) * G1_BK);
            cpa_wait1();
        } else {
            cpa_wait0();
        }
        __syncthreads();

        const int st = t & 1;
#pragma unroll
        for (int kk = 0; kk < G1_BK; kk++) {
            unsigned long long ad[8];
#pragma unroll
            for (int i = 0; i < 8; i++)
                ad[i] = dup2(As[st][(ty * 8 + i) * G1_AS + kk]);
            unsigned long long bp[4];
#pragma unroll
            for (int j = 0; j < 4; j++)
                bp[j] = *(const unsigned long long*)&Bs[st][kk * NHID + 2 * tx + 32 * j];
#pragma unroll
            for (int i = 0; i < 8; i++)
#pragma unroll
                for (int j = 0; j < 4; j++)
                    acc[i][j] = ffma2(ad[i], bp[j], acc[i][j]);
        }
        __syncthreads();
    }

#pragma unroll
    for (int i = 0; i < 8; i++) {
        int grow = row0 + ty * 8 + i;
        if (grow < NN) {
#pragma unroll
            for (int j = 0; j < 4; j++) {
                float2 v = unpack2(acc[i][j]);
                *(float2*)&g_s1[(size_t)grow * NHID + 2 * tx + 32 * j] = v;
            }
        }
    }
#undef G1_PREFETCH
}

// ---------------- SpMM1 + bias + ReLU (warp/row, f32x2 accum, 16B gathers) ----------------
__global__ void spmm1_kernel(const int* __restrict__ acol, const float* __restrict__ aval,
                             const float* __restrict__ b1) {
    int warp = (blockIdx.x * blockDim.x + threadIdx.x) >> 5;
    int lane = threadIdx.x & 31;
    if (warp >= NN) return;

    int s = g_rowptr[warp];
    int e = g_rowptr[warp + 1];

    const char* S1b = (const char*)g_s1 + (size_t)lane * 16;
    unsigned long long a01 = 0ull, a23 = 0ull;

    int i = s;
    if ((i & 1) && i < e) {
        int   c = __ldcs(&acol[i]);
        float v = __ldcs(&aval[i]);
        unsigned long long d0, d1;
        ldg128cg(S1b + (size_t)c * 512, d0, d1);
        unsigned long long vv = dup2(v);
        a01 = ffma2(vv, d0, a01);
        a23 = ffma2(vv, d1, a23);
        i++;
    }
    for (; i + 1 < e; i += 2) {
        int2   c2 = __ldcs((const int2*)&acol[i]);
        float2 v2 = __ldcs((const float2*)&aval[i]);
        unsigned long long d0, d1, e0, e1;
        ldg128cg(S1b + (size_t)c2.x * 512, d0, d1);
        ldg128cg(S1b + (size_t)c2.y * 512, e0, e1);
        unsigned long long vx = dup2(v2.x), vy = dup2(v2.y);
        a01 = ffma2(vx, d0, a01);
        a23 = ffma2(vx, d1, a23);
        a01 = ffma2(vy, e0, a01);
        a23 = ffma2(vy, e1, a23);
    }
    if (i < e) {
        int   c = __ldcs(&acol[i]);
        float v = __ldcs(&aval[i]);
        unsigned long long d0, d1;
        ldg128cg(S1b + (size_t)c * 512, d0, d1);
        unsigned long long vv = dup2(v);
        a01 = ffma2(vv, d0, a01);
        a23 = ffma2(vv, d1, a23);
    }

    float2 p01 = unpack2(a01), p23 = unpack2(a23);
    float4 b = ((const float4*)b1)[lane];
    float4 r;
    r.x = fmaxf(p01.x + b.x, 0.f);
    r.y = fmaxf(p01.y + b.y, 0.f);
    r.z = fmaxf(p23.x + b.z, 0.f);
    r.w = fmaxf(p23.y + b.w, 0.f);
    ((float4*)g_h)[(size_t)warp * 32 + lane] = r;
}

// ---------------- GEMM2: s2 = h @ W2 ----------------
// BM=192, 256 threads, thread tile 3 rows (stride 64) x 5 col-pairs (f32x2).
// 2-stage cp.async (BK=8, row stride 12 floats = 48B, cp.async-legal, conflict-free).
// smem 38.4KB -> 5-block smem cap; grid 521 -> ~3.5 blocks/SM (better than BM=256's 2.64).
#define G2_BM 192
#define G2_BK 8
#define G2_HS 12
#define G2_NT (NHID / G2_BK)     // 16
__global__ void __launch_bounds__(256) gemm2_kernel(const float* __restrict__ W2) {
    __shared__ float  Hs[2][G2_BM * G2_HS];   // 2 x 9216 B
    __shared__ float2 Wp[NHID * 20];          // 20480 B

    const int tid = threadIdx.x;
    const int pg  = tid & 3;                  // pairs pg*5 .. pg*5+4
    const int rg  = tid >> 2;                 // rows rg + 64*i, i=0..2
    const int row0 = blockIdx.x * G2_BM;

    for (int j = tid; j < NHID * 20; j += 256) {
        int k = j / 20, p = j % 20;
        Wp[j] = *(const float2*)&W2[k * NCLASS + 2 * p];
    }

    unsigned hsb = (unsigned)__cvta_generic_to_shared(&Hs[0][0]);

    // per k-tile: 192 rows x 8 floats = 384 float4; threads 0..255 take 1st 256,
    // threads 0..127 take the rest.
#define G2_PREFETCH(stage, k0)                                                     \
    do {                                                                           \
        _Pragma("unroll")                                                          \
        for (int j = 0; j < 2; j++) {                                              \
            int fi = j * 256 + tid;                                                \
            if (fi < 384) {                                                        \
                int r  = fi >> 1;                                                  \
                int c4 = (fi & 1) * 4;                                             \
                int grow = row0 + r;                                               \
                unsigned dst = hsb + (stage) * (G2_BM * G2_HS * 4) + (r * G2_HS + c4) * 4; \
                cpa16(dst, &g_h[(size_t)grow * NHID + (k0) + c4], grow < NN);      \
            }                                                                      \
        }                                                                          \
        cpa_commit();                                                              \
    } while (0)

    G2_PREFETCH(0, 0);

    unsigned long long acc[3][5];
#pragma unroll
    for (int i = 0; i < 3; i++)
#pragma unroll
        for (int j = 0; j < 5; j++) acc[i][j] = 0ull;

    for (int t = 0; t < G2_NT; t++) {
        if (t + 1 < G2_NT) {
            G2_PREFETCH((t + 1) & 1, (t + 1) * G2_BK);
            cpa_wait1();
        } else {
            cpa_wait0();
        }
        __syncthreads();

        const int st = t & 1;
        const int kbase = t * G2_BK;
#pragma unroll
        for (int kk = 0; kk < G2_BK; kk++) {
            unsigned long long hd[3];
#pragma unroll
            for (int i = 0; i < 3; i++)
                hd[i] = dup2(Hs[st][(rg + 64 * i) * G2_HS + kk]);
            unsigned long long wv[5];
#pragma unroll
            for (int j = 0; j < 5; j++)
                wv[j] = *(const unsigned long long*)&Wp[(kbase + kk) * 20 + pg * 5 + j];
#pragma unroll
            for (int i = 0; i < 3; i++)
#pragma unroll
                for (int j = 0; j < 5; j++)
                    acc[i][j] = ffma2(hd[i], wv[j], acc[i][j]);
        }
        __syncthreads();
    }

#pragma unroll
    for (int i = 0; i < 3; i++) {
        int grow = row0 + rg + 64 * i;
        if (grow < NN) {
#pragma unroll
            for (int j = 0; j < 5; j++) {
                float2 v = unpack2(acc[i][j]);
                *(float2*)&g_s2[(size_t)grow * NCLASS + 2 * (pg * 5 + j)] = v;
            }
        }
    }
#undef G2_PREFETCH
}

// ---------------- SpMM2 + bias + log_softmax (f32x2, 4-edge unroll) ----------------
__global__ void spmm2_lsm_kernel(const int* __restrict__ acol, const float* __restrict__ aval,
                                 const float* __restrict__ b2, float* __restrict__ out) {
    int warp = (blockIdx.x * blockDim.x + threadIdx.x) >> 5;
    int lane = threadIdx.x & 31;
    if (warp >= NN) return;

    int s = g_rowptr[warp];
    int e = g_rowptr[warp + 1];
    bool active = lane < 20;

    const char* S2b = (const char*)g_s2 + (size_t)lane * 8;
    unsigned long long acc = 0ull;

    int i = s;
    while (i < e && (i & 3)) {
        int   c = __ldcs(&acol[i]);
        float v = __ldcs(&aval[i]);
        if (active) acc = ffma2(dup2(v), ldg64cg(S2b + (size_t)c * 160), acc);
        i++;
    }
    for (; i + 3 < e; i += 4) {
        int4   c4 = __ldcs((const int4*)&acol[i]);
        float4 v4 = __ldcs((const float4*)&aval[i]);
        if (active) {
            unsigned long long d0 = ldg64cg(S2b + (size_t)c4.x * 160);
            unsigned long long d1 = ldg64cg(S2b + (size_t)c4.y * 160);
            unsigned long long d2 = ldg64cg(S2b + (size_t)c4.z * 160);
            unsigned long long d3 = ldg64cg(S2b + (size_t)c4.w * 160);
            acc = ffma2(dup2(v4.x), d0, acc);
            acc = ffma2(dup2(v4.y), d1, acc);
            acc = ffma2(dup2(v4.z), d2, acc);
            acc = ffma2(dup2(v4.w), d3, acc);
        }
    }
    for (; i < e; i++) {
        int   c = __ldcs(&acol[i]);
        float v = __ldcs(&aval[i]);
        if (active) acc = ffma2(dup2(v), ldg64cg(S2b + (size_t)c * 160), acc);
    }

    float2 av = unpack2(acc);
    if (active) {
        float2 bb = *(const float2*)&b2[2 * lane];
        av.x += bb.x;
        av.y += bb.y;
    }

    float m = active ? fmaxf(av.x, av.y) : -INFINITY;
#pragma unroll
    for (int off = 16; off > 0; off >>= 1)
        m = fmaxf(m, __shfl_xor_sync(0xFFFFFFFFu, m, off));

    float se = active ? (expf(av.x - m) + expf(av.y - m)) : 0.f;
#pragma unroll
    for (int off = 16; off > 0; off >>= 1)
        se += __shfl_xor_sync(0xFFFFFFFFu, se, off);

    float lse = m + logf(se);
    if (active) {
        out[(size_t)warp * NCLASS + 2 * lane]     = av.x - lse;
        out[(size_t)warp * NCLASS + 2 * lane + 1] = av.y - lse;
    }
}

// ---------------- launch ----------------
extern "C" void kernel_launch(void* const* d_in, const int* in_sizes, int n_in,
                              void* d_out, int out_size) {
    const float* x    = (const float*)d_in[0];
    const int*   arow = (const int*)  d_in[1];
    const int*   acol = (const int*)  d_in[2];
    const float* aval = (const float*)d_in[3];
    // d_in[4] = i (unused)
    const float* W1 = (const float*)d_in[5];
    const float* b1 = (const float*)d_in[6];
    const float* W2 = (const float*)d_in[7];
    const float* b2 = (const float*)d_in[8];
    float* out = (float*)d_out;

    build_rowptr_kernel<<<(NN + 1 + 255) / 256, 256>>>(arow);
    gemm1_kernel<<<(NN + G1_BM - 1) / G1_BM, 256>>>(x, W1);
    spmm1_kernel<<<(NN * 32 + 255) / 256, 256>>>(acol, aval, b1);
    gemm2_kernel<<<(NN + G2_BM - 1) / G2_BM, 256>>>(W2);
    spmm2_lsm_kernel<<<(NN * 32 + 255) / 256, 256>>>(acol, aval, b2, out);
}

// round 10
// speedup vs baseline: 1.0730x; 1.0148x over previous
#include <cuda_runtime.h>
#include <math.h>
#include <cstdint>

#define NN    100000
#define EE    3200000
#define NFEAT 256
#define NHID  128
#define NCLASS 40

// ---------------- scratch ----------------
__device__ __align__(16) float g_s1[NN * NHID];     // x @ W1 (51.2 MB)
__device__ __align__(16) float g_h [NN * NHID];     // relu(A@s1 + b1) (51.2 MB)
__device__ __align__(16) float g_s2[NN * NCLASS];   // h @ W2 (16 MB)
__device__ int g_rowptr[NN + 1];
// W1 tf32 hi/lo fragment image: 16 chunks x 16KB (fragment-ordered for m16n8k8)
__device__ __align__(16) uint32_t g_Btf[65536];

// ---------------- f32x2 packed helpers ----------------
__device__ __forceinline__ unsigned long long ffma2(unsigned long long a,
                                                    unsigned long long b,
                                                    unsigned long long c) {
    unsigned long long d;
    asm("fma.rn.f32x2 %0, %1, %2, %3;" : "=l"(d) : "l"(a), "l"(b), "l"(c));
    return d;
}
__device__ __forceinline__ unsigned long long dup2(float a) {
    unsigned long long d;
    asm("mov.b64 %0, {%1, %1};" : "=l"(d) : "f"(a));
    return d;
}
__device__ __forceinline__ float2 unpack2(unsigned long long v) {
    float2 f;
    asm("mov.b64 {%0, %1}, %2;" : "=f"(f.x), "=f"(f.y) : "l"(v));
    return f;
}
__device__ __forceinline__ unsigned long long ldg64cg(const void* p) {
    unsigned long long v;
    asm volatile("ld.global.cg.b64 %0, [%1];" : "=l"(v) : "l"(p));
    return v;
}
__device__ __forceinline__ void ldg128cg(const void* p, unsigned long long& a,
                                         unsigned long long& b) {
    asm volatile("ld.global.cg.v2.u64 {%0, %1}, [%2];" : "=l"(a), "=l"(b) : "l"(p));
}

// ---------------- cp.async helpers ----------------
__device__ __forceinline__ void cpa16(unsigned dst, const void* src, bool pred) {
    int sz = pred ? 16 : 0;
    asm volatile("cp.async.ca.shared.global [%0], [%1], 16, %2;\n"
                 :: "r"(dst), "l"(src), "r"(sz));
}
__device__ __forceinline__ void cpa_commit() { asm volatile("cp.async.commit_group;\n"); }
__device__ __forceinline__ void cpa_wait1()  { asm volatile("cp.async.wait_group 1;\n"); }
__device__ __forceinline__ void cpa_wait0()  { asm volatile("cp.async.wait_group 0;\n"); }

// ---------------- tf32 helpers ----------------
__device__ __forceinline__ uint32_t to_tf32(float x) {
    uint32_t u;
    asm("cvt.rna.tf32.f32 %0, %1;" : "=r"(u) : "f"(x));
    return u;
}
#define MMA_TF32(d, a, b)                                                        \
    asm volatile("mma.sync.aligned.m16n8k8.row.col.f32.tf32.tf32.f32 "          \
        "{%0,%1,%2,%3}, {%4,%5,%6,%7}, {%8,%9}, {%0,%1,%2,%3};"                 \
        : "+f"((d)[0]), "+f"((d)[1]), "+f"((d)[2]), "+f"((d)[3])                \
        : "r"((a).x), "r"((a).y), "r"((a).z), "r"((a).w), "r"((b).x), "r"((b).y))

// ---------------- CSR row_ptr ----------------
__global__ void build_rowptr_kernel(const int* __restrict__ arow) {
    int r = blockIdx.x * blockDim.x + threadIdx.x;
    if (r > NN) return;
    int lo = 0, hi = EE;
    while (lo < hi) {
        int mid = (lo + hi) >> 1;
        if (arow[mid] < r) lo = mid + 1; else hi = mid;
    }
    g_rowptr[r] = lo;
}

// ---------------- W1 -> tf32 hi/lo fragment image ----------------
// Per chunk c (k in [16c,16c+16)): layout [ct(16)][k8(2)][h(2)][lane(32)][reg(2)] u32.
__global__ void w1tf32_kernel(const float* __restrict__ W1) {
    int idx = blockIdx.x * blockDim.x + threadIdx.x;
    if (idx >= NFEAT * NHID) return;
    int k = idx >> 7, n = idx & 127;
    float w = W1[idx];
    uint32_t hi = to_tf32(w);
    uint32_t lo = to_tf32(w - __uint_as_float(hi));
    int chunk = k >> 4, kk = k & 15;
    int ct = n >> 3, gid = n & 7;
    int k8 = kk >> 3, k2 = kk & 7;
    int tig = k2 & 3, b1f = k2 >> 2;
    int l = gid * 4 + tig;
    int base = chunk * 4096 + (((ct * 2 + k8) * 2) * 32 + l) * 2 + b1f;
    g_Btf[base]      = hi;   // h=0
    g_Btf[base + 64] = lo;   // h=1 (+32 lanes * 2 regs)
}

// ---------------- GEMM1 (mma.sync tf32 hi/lo): g_s1 = X @ W1 ----------------
// 128x128 tile/CTA, 8 warps in 4x2 (32 rows x 64 cols each). Per chunk (k=16):
// A split/staged fragment-ordered in sA; B image cp.async double-buffered.
// 3 passes accumulate into one D: Ahi*Bhi + Ahi*Blo + Alo*Bhi.
__global__ void __launch_bounds__(256, 2) gemm1_tf32_kernel(const float* __restrict__ X) {
    __shared__ __align__(16) uint32_t sA[4096];       // 16KB [rt8][k8:2][h2][lane32][reg4]
    __shared__ __align__(16) uint32_t sB[2][4096];    // 2 x 16KB

    const int tid  = threadIdx.x;
    const int lane = tid & 31;
    const int warp = tid >> 5;
    const int wrow = (warp >> 1) * 32;
    const int wcol = (warp & 1) * 64;
    const int row0 = blockIdx.x * 128;

    unsigned sb_addr = (unsigned)__cvta_generic_to_shared(&sB[0][0]);

    float acc[2][8][4];
#pragma unroll
    for (int r = 0; r < 2; r++)
#pragma unroll
        for (int c = 0; c < 8; c++)
#pragma unroll
            for (int j = 0; j < 4; j++) acc[r][c][j] = 0.f;

    const int srow = tid >> 1;
    const int skp  = (tid & 1) * 8;
    const int sgrow = row0 + srow;

    float4 xa, xb;
    {   // preload chunk 0
        const float* p = X + (size_t)sgrow * NFEAT + skp;
        if (sgrow < NN) { xa = *(const float4*)p; xb = *(const float4*)(p + 4); }
        else { xa = make_float4(0.f, 0.f, 0.f, 0.f); xb = xa; }
    }
#pragma unroll
    for (int j = 0; j < 4; j++)
        cpa16(sb_addr + tid * 16 + j * 4096, (const char*)g_Btf + tid * 16 + j * 4096, true);
    cpa_commit();

    for (int t = 0; t < 16; t++) {
        __syncthreads();                        // prev MMA done: sA + sB[(t+1)&1] reusable
        if (t + 1 < 16) {
            int st1 = (t + 1) & 1;
#pragma unroll
            for (int j = 0; j < 4; j++)
                cpa16(sb_addr + st1 * 16384 + tid * 16 + j * 4096,
                      (const char*)g_Btf + (t + 1) * 16384 + tid * 16 + j * 4096, true);
            cpa_commit();
        }
        // convert registers -> sA fragment image
        {
            float xs[8] = {xa.x, xa.y, xa.z, xa.w, xb.x, xb.y, xb.z, xb.w};
            int rt = srow >> 4, r16 = srow & 15;
            int gid = r16 & 7, a1f = r16 >> 3;
#pragma unroll
            for (int q = 0; q < 8; q++) {
                int kk = skp + q;
                int k8 = kk >> 3, k2 = kk & 7;
                int tig = k2 & 3, a2f = k2 >> 2;
                int l = gid * 4 + tig;
                int reg = a2f * 2 + a1f;
                uint32_t hi = to_tf32(xs[q]);
                uint32_t lo = to_tf32(xs[q] - __uint_as_float(hi));
                int base = (((rt * 2 + k8) * 2) * 32 + l) * 4 + reg;
                sA[base]       = hi;            // h=0
                sA[base + 128] = lo;            // h=1 (+32 lanes * 4 regs)
            }
        }
        if (t + 1 < 16) {
            const float* p = X + (size_t)sgrow * NFEAT + (t + 1) * 16 + skp;
            if (sgrow < NN) { xa = *(const float4*)p; xb = *(const float4*)(p + 4); }
            else { xa = make_float4(0.f, 0.f, 0.f, 0.f); xb = xa; }
            cpa_wait1();
        } else {
            cpa_wait0();
        }
        __syncthreads();                        // sA + sB[t&1] ready

        const uint32_t* sBc = sB[t & 1];
        const uint4* sA4 = (const uint4*)sA;
        const uint2* sB2 = (const uint2*)sBc;
        const int rtb = wrow >> 4;
        const int ctb = wcol >> 3;
#pragma unroll
        for (int k8 = 0; k8 < 2; k8++) {
            uint4 ahi[2], alo[2];
#pragma unroll
            for (int r = 0; r < 2; r++) {
                int rt = rtb + r;
                ahi[r] = sA4[((rt * 2 + k8) * 2 + 0) * 32 + lane];
                alo[r] = sA4[((rt * 2 + k8) * 2 + 1) * 32 + lane];
            }
#pragma unroll
            for (int c = 0; c < 8; c++) {
                int ct = ctb + c;
                uint2 bhi = sB2[((ct * 2 + k8) * 2 + 0) * 32 + lane];
                uint2 blo = sB2[((ct * 2 + k8) * 2 + 1) * 32 + lane];
#pragma unroll
                for (int r = 0; r < 2; r++) {
                    MMA_TF32(acc[r][c], ahi[r], bhi);
                    MMA_TF32(acc[r][c], ahi[r], blo);
                    MMA_TF32(acc[r][c], alo[r], bhi);
                }
            }
        }
    }

    // store D
    const int gid = lane >> 2, tig = lane & 3;
#pragma unroll
    for (int r = 0; r < 2; r++) {
        int rbase = row0 + wrow + r * 16;
#pragma unroll
        for (int c = 0; c < 8; c++) {
            int col = wcol + c * 8 + tig * 2;
            int ra = rbase + gid, rb = rbase + gid + 8;
            if (ra < NN)
                *(float2*)&g_s1[(size_t)ra * NHID + col] = make_float2(acc[r][c][0], acc[r][c][1]);
            if (rb < NN)
                *(float2*)&g_s1[(size_t)rb * NHID + col] = make_float2(acc[r][c][2], acc[r][c][3]);
        }
    }
}

// ---------------- SpMM1 + bias + ReLU (warp/row, f32x2 accum, 16B gathers) ----------------
__global__ void spmm1_kernel(const int* __restrict__ acol, const float* __restrict__ aval,
                             const float* __restrict__ b1) {
    int warp = (blockIdx.x * blockDim.x + threadIdx.x) >> 5;
    int lane = threadIdx.x & 31;
    if (warp >= NN) return;

    int s = g_rowptr[warp];
    int e = g_rowptr[warp + 1];

    const char* S1b = (const char*)g_s1 + (size_t)lane * 16;
    unsigned long long a01 = 0ull, a23 = 0ull;

    int i = s;
    if ((i & 1) && i < e) {
        int   c = __ldcs(&acol[i]);
        float v = __ldcs(&aval[i]);
        unsigned long long d0, d1;
        ldg128cg(S1b + (size_t)c * 512, d0, d1);
        unsigned long long vv = dup2(v);
        a01 = ffma2(vv, d0, a01);
        a23 = ffma2(vv, d1, a23);
        i++;
    }
    for (; i + 1 < e; i += 2) {
        int2   c2 = __ldcs((const int2*)&acol[i]);
        float2 v2 = __ldcs((const float2*)&aval[i]);
        unsigned long long d0, d1, e0, e1;
        ldg128cg(S1b + (size_t)c2.x * 512, d0, d1);
        ldg128cg(S1b + (size_t)c2.y * 512, e0, e1);
        unsigned long long vx = dup2(v2.x), vy = dup2(v2.y);
        a01 = ffma2(vx, d0, a01);
        a23 = ffma2(vx, d1, a23);
        a01 = ffma2(vy, e0, a01);
        a23 = ffma2(vy, e1, a23);
    }
    if (i < e) {
        int   c = __ldcs(&acol[i]);
        float v = __ldcs(&aval[i]);
        unsigned long long d0, d1;
        ldg128cg(S1b + (size_t)c * 512, d0, d1);
        unsigned long long vv = dup2(v);
        a01 = ffma2(vv, d0, a01);
        a23 = ffma2(vv, d1, a23);
    }

    float2 p01 = unpack2(a01), p23 = unpack2(a23);
    float4 b = ((const float4*)b1)[lane];
    float4 r;
    r.x = fmaxf(p01.x + b.x, 0.f);
    r.y = fmaxf(p01.y + b.y, 0.f);
    r.z = fmaxf(p23.x + b.z, 0.f);
    r.w = fmaxf(p23.y + b.w, 0.f);
    ((float4*)g_h)[(size_t)warp * 32 + lane] = r;
}

// ---------------- GEMM2: s2 = h @ W2 (BM=256, BK=8, 2-stage cp.async) ----------------
#define G2_BM 256
#define G2_BK 8
#define G2_HS 12
#define G2_NT (NHID / G2_BK)     // 16
__global__ void __launch_bounds__(256) gemm2_kernel(const float* __restrict__ W2) {
    __shared__ float  Hs[2][G2_BM * G2_HS];
    __shared__ float2 Wp[NHID * 20];

    const int tid = threadIdx.x;
    const int pg  = tid & 3;
    const int rg  = tid >> 2;
    const int row0 = blockIdx.x * G2_BM;

    for (int j = tid; j < NHID * 20; j += 256) {
        int k = j / 20, p = j % 20;
        Wp[j] = *(const float2*)&W2[k * NCLASS + 2 * p];
    }

    unsigned hsb = (unsigned)__cvta_generic_to_shared(&Hs[0][0]);

#define G2_PREFETCH(stage, k0)                                                     \
    do {                                                                           \
        _Pragma("unroll")                                                          \
        for (int j = 0; j < 2; j++) {                                              \
            int fi = j * 256 + tid;                                                \
            int r  = fi >> 1;                                                      \
            int c4 = (fi & 1) * 4;                                                 \
            int grow = row0 + r;                                                   \
            unsigned dst = hsb + (stage) * (G2_BM * G2_HS * 4) + (r * G2_HS + c4) * 4; \
            cpa16(dst, &g_h[(size_t)grow * NHID + (k0) + c4], grow < NN);          \
        }                                                                          \
        cpa_commit();                                                              \
    } while (0)

    G2_PREFETCH(0, 0);

    unsigned long long acc[4][5];
#pragma unroll
    for (int i = 0; i < 4; i++)
#pragma unroll
        for (int j = 0; j < 5; j++) acc[i][j] = 0ull;

    for (int t = 0; t < G2_NT; t++) {
        if (t + 1 < G2_NT) {
            G2_PREFETCH((t + 1) & 1, (t + 1) * G2_BK);
            cpa_wait1();
        } else {
            cpa_wait0();
        }
        __syncthreads();

        const int st = t & 1;
        const int kbase = t * G2_BK;
#pragma unroll
        for (int kk = 0; kk < G2_BK; kk++) {
            unsigned long long hd[4];
#pragma unroll
            for (int i = 0; i < 4; i++)
                hd[i] = dup2(Hs[st][(rg + 64 * i) * G2_HS + kk]);
            unsigned long long wv[5];
#pragma unroll
            for (int j = 0; j < 5; j++)
                wv[j] = *(const unsigned long long*)&Wp[(kbase + kk) * 20 + pg * 5 + j];
#pragma unroll
            for (int i = 0; i < 4; i++)
#pragma unroll
                for (int j = 0; j < 5; j++)
                    acc[i][j] = ffma2(hd[i], wv[j], acc[i][j]);
        }
        __syncthreads();
    }

#pragma unroll
    for (int i = 0; i < 4; i++) {
        int grow = row0 + rg + 64 * i;
        if (grow < NN) {
#pragma unroll
            for (int j = 0; j < 5; j++) {
                float2 v = unpack2(acc[i][j]);
                *(float2*)&g_s2[(size_t)grow * NCLASS + 2 * (pg * 5 + j)] = v;
            }
        }
    }
#undef G2_PREFETCH
}

// ---------------- SpMM2 + bias + log_softmax (f32x2, 4-edge unroll) ----------------
__global__ void spmm2_lsm_kernel(const int* __restrict__ acol, const float* __restrict__ aval,
                                 const float* __restrict__ b2, float* __restrict__ out) {
    int warp = (blockIdx.x * blockDim.x + threadIdx.x) >> 5;
    int lane = threadIdx.x & 31;
    if (warp >= NN) return;

    int s = g_rowptr[warp];
    int e = g_rowptr[warp + 1];
    bool active = lane < 20;

    const char* S2b = (const char*)g_s2 + (size_t)lane * 8;
    unsigned long long acc = 0ull;

    int i = s;
    while (i < e && (i & 3)) {
        int   c = __ldcs(&acol[i]);
        float v = __ldcs(&aval[i]);
        if (active) acc = ffma2(dup2(v), ldg64cg(S2b + (size_t)c * 160), acc);
        i++;
    }
    for (; i + 3 < e; i += 4) {
        int4   c4 = __ldcs((const int4*)&acol[i]);
        float4 v4 = __ldcs((const float4*)&aval[i]);
        if (active) {
            unsigned long long d0 = ldg64cg(S2b + (size_t)c4.x * 160);
            unsigned long long d1 = ldg64cg(S2b + (size_t)c4.y * 160);
            unsigned long long d2 = ldg64cg(S2b + (size_t)c4.z * 160);
            unsigned long long d3 = ldg64cg(S2b + (size_t)c4.w * 160);
            acc = ffma2(dup2(v4.x), d0, acc);
            acc = ffma2(dup2(v4.y), d1, acc);
            acc = ffma2(dup2(v4.z), d2, acc);
            acc = ffma2(dup2(v4.w), d3, acc);
        }
    }
    for (; i < e; i++) {
        int   c = __ldcs(&acol[i]);
        float v = __ldcs(&aval[i]);
        if (active) acc = ffma2(dup2(v), ldg64cg(S2b + (size_t)c * 160), acc);
    }

    float2 av = unpack2(acc);
    if (active) {
        float2 bb = *(const float2*)&b2[2 * lane];
        av.x += bb.x;
        av.y += bb.y;
    }

    float m = active ? fmaxf(av.x, av.y) : -INFINITY;
#pragma unroll
    for (int off = 16; off > 0; off >>= 1)
        m = fmaxf(m, __shfl_xor_sync(0xFFFFFFFFu, m, off));

    float se = active ? (expf(av.x - m) + expf(av.y - m)) : 0.f;
#pragma unroll
    for (int off = 16; off > 0; off >>= 1)
        se += __shfl_xor_sync(0xFFFFFFFFu, se, off);

    float lse = m + logf(se);
    if (active) {
        out[(size_t)warp * NCLASS + 2 * lane]     = av.x - lse;
        out[(size_t)warp * NCLASS + 2 * lane + 1] = av.y - lse;
    }
}

// ---------------- launch ----------------
extern "C" void kernel_launch(void* const* d_in, const int* in_sizes, int n_in,
                              void* d_out, int out_size) {
    const float* x    = (const float*)d_in[0];
    const int*   arow = (const int*)  d_in[1];
    const int*   acol = (const int*)  d_in[2];
    const float* aval = (const float*)d_in[3];
    // d_in[4] = i (unused)
    const float* W1 = (const float*)d_in[5];
    const float* b1 = (const float*)d_in[6];
    const float* W2 = (const float*)d_in[7];
    const float* b2 = (const float*)d_in[8];
    float* out = (float*)d_out;

    build_rowptr_kernel<<<(NN + 1 + 255) / 256, 256>>>(arow);
    w1tf32_kernel<<<(NFEAT * NHID + 255) / 256, 256>>>(W1);
    gemm1_tf32_kernel<<<(NN + 127) / 128, 256>>>(x);
    spmm1_kernel<<<(NN * 32 + 255) / 256, 256>>>(acol, aval, b1);
    gemm2_kernel<<<(NN + G2_BM - 1) / G2_BM, 256>>>(W2);
    spmm2_lsm_kernel<<<(NN * 32 + 255) / 256, 256>>>(acol, aval, b2, out);
}

// round 11
// speedup vs baseline: 1.2312x; 1.1474x over previous
#include <cuda_runtime.h>
#include <math.h>
#include <cstdint>

#define NN    100000
#define EE    3200000
#define NFEAT 256
#define NHID  128
#define NCLASS 40

// ---------------- scratch ----------------
__device__ __align__(16) float g_s1[NN * NHID];     // x @ W1 (51.2 MB)
__device__ __align__(16) float g_h [NN * NHID];     // relu(A@s1 + b1) (51.2 MB)
__device__ __align__(16) float g_s2[NN * NCLASS];   // h @ W2 (16 MB)
__device__ int g_rowptr[NN + 1];
// W1 bf16 hi/lo fragment image for m16n8k16: [c16(16)][ct(16)][h(2)][lane(32)][reg(2)] u32
__device__ __align__(16) uint32_t g_Bbf[32768];     // 128 KB

// ---------------- f32x2 packed helpers ----------------
__device__ __forceinline__ unsigned long long ffma2(unsigned long long a,
                                                    unsigned long long b,
                                                    unsigned long long c) {
    unsigned long long d;
    asm("fma.rn.f32x2 %0, %1, %2, %3;" : "=l"(d) : "l"(a), "l"(b), "l"(c));
    return d;
}
__device__ __forceinline__ unsigned long long dup2(float a) {
    unsigned long long d;
    asm("mov.b64 %0, {%1, %1};" : "=l"(d) : "f"(a));
    return d;
}
__device__ __forceinline__ float2 unpack2(unsigned long long v) {
    float2 f;
    asm("mov.b64 {%0, %1}, %2;" : "=f"(f.x), "=f"(f.y) : "l"(v));
    return f;
}
__device__ __forceinline__ unsigned long long ldg64cg(const void* p) {
    unsigned long long v;
    asm volatile("ld.global.cg.b64 %0, [%1];" : "=l"(v) : "l"(p));
    return v;
}
__device__ __forceinline__ void ldg128cg(const void* p, unsigned long long& a,
                                         unsigned long long& b) {
    asm volatile("ld.global.cg.v2.u64 {%0, %1}, [%2];" : "=l"(a), "=l"(b) : "l"(p));
}

// ---------------- cp.async helpers ----------------
__device__ __forceinline__ void cpa16(unsigned dst, const void* src, bool pred) {
    int sz = pred ? 16 : 0;
    asm volatile("cp.async.ca.shared.global [%0], [%1], 16, %2;\n"
                 :: "r"(dst), "l"(src), "r"(sz));
}
__device__ __forceinline__ void cpa_commit() { asm volatile("cp.async.commit_group;\n"); }
__device__ __forceinline__ void cpa_wait1()  { asm volatile("cp.async.wait_group 1;\n"); }
__device__ __forceinline__ void cpa_wait0()  { asm volatile("cp.async.wait_group 0;\n"); }

// ---------------- bf16 helpers ----------------
__device__ __forceinline__ uint32_t pack2bf(float2 v) {      // low16=bf16(v.x), high16=bf16(v.y)
    uint32_t d;
    asm("cvt.rn.bf16x2.f32 %0, %1, %2;" : "=r"(d) : "f"(v.y), "f"(v.x));
    return d;
}
__device__ __forceinline__ uint32_t pack2bf_lo(float2 v, uint32_t h) {
    float fx = __uint_as_float(h << 16);
    float fy = __uint_as_float(h & 0xFFFF0000u);
    float2 r = make_float2(v.x - fx, v.y - fy);
    return pack2bf(r);
}
#define MMA_BF16(d, a0, a1, a2, a3, b0, b1)                                      \
    asm volatile("mma.sync.aligned.m16n8k16.row.col.f32.bf16.bf16.f32 "         \
        "{%0,%1,%2,%3}, {%4,%5,%6,%7}, {%8,%9}, {%0,%1,%2,%3};"                 \
        : "+f"((d)[0]), "+f"((d)[1]), "+f"((d)[2]), "+f"((d)[3])                \
        : "r"(a0), "r"(a1), "r"(a2), "r"(a3), "r"(b0), "r"(b1))

// ---------------- CSR row_ptr ----------------
__global__ void build_rowptr_kernel(const int* __restrict__ arow) {
    int r = blockIdx.x * blockDim.x + threadIdx.x;
    if (r > NN) return;
    int lo = 0, hi = EE;
    while (lo < hi) {
        int mid = (lo + hi) >> 1;
        if (arow[mid] < r) lo = mid + 1; else hi = mid;
    }
    g_rowptr[r] = lo;
}

// ---------------- W1 -> bf16 hi/lo fragment image (m16n8k16, col-major B) ----------------
// b0 = W1[k16base + tig*2 + {0,1}][col], b1 = W1[k16base + tig*2+8 + {0,1}][col]
__global__ void w1bf16_kernel(const float* __restrict__ W1) {
    int idx = blockIdx.x * blockDim.x + threadIdx.x;
    if (idx >= NFEAT * NHID) return;
    int k = idx >> 7, n = idx & 127;
    float w = W1[idx];
    uint32_t hp = pack2bf(make_float2(w, 0.f));          // low16 = bf16(w)
    unsigned short hi16 = (unsigned short)(hp & 0xFFFFu);
    float fh = __uint_as_float((uint32_t)hi16 << 16);
    uint32_t lp = pack2bf(make_float2(w - fh, 0.f));
    unsigned short lo16 = (unsigned short)(lp & 0xFFFFu);

    int c16 = k >> 4, kk = k & 15;
    int ct = n >> 3, gid = n & 7;
    int reg = kk >> 3;
    int tig = (kk & 7) >> 1;
    int pos = kk & 1;
    int lane = gid * 4 + tig;
    // u16 index: [c16][ct][h][lane][reg][pos]
    int base16 = ((((c16 * 16 + ct) * 2 + 0) * 32 + lane) * 2 + reg) * 2 + pos;
    unsigned short* B16 = (unsigned short*)g_Bbf;
    B16[base16]       = hi16;     // h = 0
    B16[base16 + 128] = lo16;     // h = 1 (+32 lanes * 2 regs * 2 pos)
}

// ---------------- GEMM1 (mma.sync bf16 hi/lo): g_s1 = X @ W1 ----------------
// 128x128 tile/CTA, 8 warps in 4x2 (32 rows x 64 cols). A fragments loaded
// DIRECTLY from X (no smem stage), converted in regs. B image cp.async
// double-buffered, stage = 32 k (2 k16 steps). 3 passes: Ahi*Bhi+Ahi*Blo+Alo*Bhi.
__global__ void __launch_bounds__(256) gemm1_bf16_kernel(const float* __restrict__ X) {
    __shared__ __align__(16) uint32_t sB[2][4096];   // 2 x 16KB

    const int tid  = threadIdx.x;
    const int lane = tid & 31;
    const int warp = tid >> 5;
    const int wrow = (warp >> 1) * 32;
    const int wcol = (warp & 1) * 64;
    const int row0 = blockIdx.x * 128;
    const int gid  = lane >> 2;
    const int tig  = lane & 3;
    const int ctb  = wcol >> 3;

    unsigned sb_addr = (unsigned)__cvta_generic_to_shared(&sB[0][0]);

    // row indices + guards for the 4 rows this lane touches
    int rowi[2][2];
    bool rokg[2][2];
#pragma unroll
    for (int r = 0; r < 2; r++)
#pragma unroll
        for (int p = 0; p < 2; p++) {
            rowi[r][p] = row0 + wrow + r * 16 + gid + p * 8;
            rokg[r][p] = rowi[r][p] < NN;
        }

    float acc[2][8][4];
#pragma unroll
    for (int r = 0; r < 2; r++)
#pragma unroll
        for (int c = 0; c < 8; c++)
#pragma unroll
            for (int j = 0; j < 4; j++) acc[r][c][j] = 0.f;

#define G1_PREFETCH(stage, s)                                                    \
    do {                                                                         \
        _Pragma("unroll")                                                        \
        for (int j = 0; j < 4; j++) {                                            \
            int off = (j * 256 + tid) * 16;                                      \
            cpa16(sb_addr + (stage) * 16384 + off,                               \
                  (const char*)g_Bbf + (s) * 16384 + off, true);                 \
        }                                                                        \
        cpa_commit();                                                            \
    } while (0)

    G1_PREFETCH(0, 0);

    for (int s = 0; s < 8; s++) {
        if (s + 1 < 8) { G1_PREFETCH((s + 1) & 1, s + 1); cpa_wait1(); }
        else           { cpa_wait0(); }
        __syncthreads();

        // load all A fragments for this stage (16 float2, batched for MLP)
        float2 src[2][2][2][2];   // [sub][rt][rowpair][kpair]
#pragma unroll
        for (int sub = 0; sub < 2; sub++)
#pragma unroll
            for (int r = 0; r < 2; r++)
#pragma unroll
                for (int p = 0; p < 2; p++)
#pragma unroll
                    for (int q = 0; q < 2; q++) {
                        int kidx = s * 32 + sub * 16 + tig * 2 + q * 8;
                        src[sub][r][p][q] = rokg[r][p]
                            ? __ldg((const float2*)&X[(size_t)rowi[r][p] * NFEAT + kidx])
                            : make_float2(0.f, 0.f);
                    }

        const uint2* Bst = (const uint2*)&sB[s & 1][0];
#pragma unroll
        for (int sub = 0; sub < 2; sub++) {
            uint32_t ah[2][4], al[2][4];
#pragma unroll
            for (int r = 0; r < 2; r++) {
                // a0: row gid k{0,1}; a1: row gid+8 k{0,1}; a2: row gid k{8,9}; a3: row gid+8 k{8,9}
                ah[r][0] = pack2bf(src[sub][r][0][0]);
                ah[r][1] = pack2bf(src[sub][r][1][0]);
                ah[r][2] = pack2bf(src[sub][r][0][1]);
                ah[r][3] = pack2bf(src[sub][r][1][1]);
                al[r][0] = pack2bf_lo(src[sub][r][0][0], ah[r][0]);
                al[r][1] = pack2bf_lo(src[sub][r][1][0], ah[r][1]);
                al[r][2] = pack2bf_lo(src[sub][r][0][1], ah[r][2]);
                al[r][3] = pack2bf_lo(src[sub][r][1][1], ah[r][3]);
            }
#pragma unroll
            for (int c = 0; c < 8; c++) {
                int ctg = ctb + c;
                uint2 bhi = Bst[sub * 1024 + (ctg * 2 + 0) * 32 + lane];
                uint2 blo = Bst[sub * 1024 + (ctg * 2 + 1) * 32 + lane];
#pragma unroll
                for (int r = 0; r < 2; r++) {
                    MMA_BF16(acc[r][c], ah[r][0], ah[r][1], ah[r][2], ah[r][3], bhi.x, bhi.y);
                    MMA_BF16(acc[r][c], ah[r][0], ah[r][1], ah[r][2], ah[r][3], blo.x, blo.y);
                    MMA_BF16(acc[r][c], al[r][0], al[r][1], al[r][2], al[r][3], bhi.x, bhi.y);
                }
            }
        }
        __syncthreads();
    }

    // store D: c0,c1 -> row gid cols tig*2,+1; c2,c3 -> row gid+8
#pragma unroll
    for (int r = 0; r < 2; r++) {
#pragma unroll
        for (int c = 0; c < 8; c++) {
            int col = wcol + c * 8 + tig * 2;
            if (rokg[r][0])
                *(float2*)&g_s1[(size_t)rowi[r][0] * NHID + col] =
                    make_float2(acc[r][c][0], acc[r][c][1]);
            if (rokg[r][1])
                *(float2*)&g_s1[(size_t)rowi[r][1] * NHID + col] =
                    make_float2(acc[r][c][2], acc[r][c][3]);
        }
    }
#undef G1_PREFETCH
}

// ---------------- SpMM1 + bias + ReLU (warp/row, f32x2 accum, 16B gathers) ----------------
__global__ void spmm1_kernel(const int* __restrict__ acol, const float* __restrict__ aval,
                             const float* __restrict__ b1) {
    int warp = (blockIdx.x * blockDim.x + threadIdx.x) >> 5;
    int lane = threadIdx.x & 31;
    if (warp >= NN) return;

    int s = g_rowptr[warp];
    int e = g_rowptr[warp + 1];

    const char* S1b = (const char*)g_s1 + (size_t)lane * 16;
    unsigned long long a01 = 0ull, a23 = 0ull;

    int i = s;
    if ((i & 1) && i < e) {
        int   c = __ldcs(&acol[i]);
        float v = __ldcs(&aval[i]);
        unsigned long long d0, d1;
        ldg128cg(S1b + (size_t)c * 512, d0, d1);
        unsigned long long vv = dup2(v);
        a01 = ffma2(vv, d0, a01);
        a23 = ffma2(vv, d1, a23);
        i++;
    }
    for (; i + 1 < e; i += 2) {
        int2   c2 = __ldcs((const int2*)&acol[i]);
        float2 v2 = __ldcs((const float2*)&aval[i]);
        unsigned long long d0, d1, e0, e1;
        ldg128cg(S1b + (size_t)c2.x * 512, d0, d1);
        ldg128cg(S1b + (size_t)c2.y * 512, e0, e1);
        unsigned long long vx = dup2(v2.x), vy = dup2(v2.y);
        a01 = ffma2(vx, d0, a01);
        a23 = ffma2(vx, d1, a23);
        a01 = ffma2(vy, e0, a01);
        a23 = ffma2(vy, e1, a23);
    }
    if (i < e) {
        int   c = __ldcs(&acol[i]);
        float v = __ldcs(&aval[i]);
        unsigned long long d0, d1;
        ldg128cg(S1b + (size_t)c * 512, d0, d1);
        unsigned long long vv = dup2(v);
        a01 = ffma2(vv, d0, a01);
        a23 = ffma2(vv, d1, a23);
    }

    float2 p01 = unpack2(a01), p23 = unpack2(a23);
    float4 b = ((const float4*)b1)[lane];
    float4 r;
    r.x = fmaxf(p01.x + b.x, 0.f);
    r.y = fmaxf(p01.y + b.y, 0.f);
    r.z = fmaxf(p23.x + b.z, 0.f);
    r.w = fmaxf(p23.y + b.w, 0.f);
    ((float4*)g_h)[(size_t)warp * 32 + lane] = r;
}

// ---------------- GEMM2: s2 = h @ W2 (BM=256, BK=8, 2-stage cp.async) ----------------
#define G2_BM 256
#define G2_BK 8
#define G2_HS 12
#define G2_NT (NHID / G2_BK)     // 16
__global__ void __launch_bounds__(256) gemm2_kernel(const float* __restrict__ W2) {
    __shared__ float  Hs[2][G2_BM * G2_HS];
    __shared__ float2 Wp[NHID * 20];

    const int tid = threadIdx.x;
    const int pg  = tid & 3;
    const int rg  = tid >> 2;
    const int row0 = blockIdx.x * G2_BM;

    for (int j = tid; j < NHID * 20; j += 256) {
        int k = j / 20, p = j % 20;
        Wp[j] = *(const float2*)&W2[k * NCLASS + 2 * p];
    }

    unsigned hsb = (unsigned)__cvta_generic_to_shared(&Hs[0][0]);

#define G2_PREFETCH(stage, k0)                                                     \
    do {                                                                           \
        _Pragma("unroll")                                                          \
        for (int j = 0; j < 2; j++) {                                              \
            int fi = j * 256 + tid;                                                \
            int r  = fi >> 1;                                                      \
            int c4 = (fi & 1) * 4;                                                 \
            int grow = row0 + r;                                                   \
            unsigned dst = hsb + (stage) * (G2_BM * G2_HS * 4) + (r * G2_HS + c4) * 4; \
            cpa16(dst, &g_h[(size_t)grow * NHID + (k0) + c4], grow < NN);          \
        }                                                                          \
        cpa_commit();                                                              \
    } while (0)

    G2_PREFETCH(0, 0);

    unsigned long long acc[4][5];
#pragma unroll
    for (int i = 0; i < 4; i++)
#pragma unroll
        for (int j = 0; j < 5; j++) acc[i][j] = 0ull;

    for (int t = 0; t < G2_NT; t++) {
        if (t + 1 < G2_NT) {
            G2_PREFETCH((t + 1) & 1, (t + 1) * G2_BK);
            cpa_wait1();
        } else {
            cpa_wait0();
        }
        __syncthreads();

        const int st = t & 1;
        const int kbase = t * G2_BK;
#pragma unroll
        for (int kk = 0; kk < G2_BK; kk++) {
            unsigned long long hd[4];
#pragma unroll
            for (int i = 0; i < 4; i++)
                hd[i] = dup2(Hs[st][(rg + 64 * i) * G2_HS + kk]);
            unsigned long long wv[5];
#pragma unroll
            for (int j = 0; j < 5; j++)
                wv[j] = *(const unsigned long long*)&Wp[(kbase + kk) * 20 + pg * 5 + j];
#pragma unroll
            for (int i = 0; i < 4; i++)
#pragma unroll
                for (int j = 0; j < 5; j++)
                    acc[i][j] = ffma2(hd[i], wv[j], acc[i][j]);
        }
        __syncthreads();
    }

#pragma unroll
    for (int i = 0; i < 4; i++) {
        int grow = row0 + rg + 64 * i;
        if (grow < NN) {
#pragma unroll
            for (int j = 0; j < 5; j++) {
                float2 v = unpack2(acc[i][j]);
                *(float2*)&g_s2[(size_t)grow * NCLASS + 2 * (pg * 5 + j)] = v;
            }
        }
    }
#undef G2_PREFETCH
}

// ---------------- SpMM2 + bias + log_softmax (f32x2, 4-edge unroll) ----------------
__global__ void spmm2_lsm_kernel(const int* __restrict__ acol, const float* __restrict__ aval,
                                 const float* __restrict__ b2, float* __restrict__ out) {
    int warp = (blockIdx.x * blockDim.x + threadIdx.x) >> 5;
    int lane = threadIdx.x & 31;
    if (warp >= NN) return;

    int s = g_rowptr[warp];
    int e = g_rowptr[warp + 1];
    bool active = lane < 20;

    const char* S2b = (const char*)g_s2 + (size_t)lane * 8;
    unsigned long long acc = 0ull;

    int i = s;
    while (i < e && (i & 3)) {
        int   c = __ldcs(&acol[i]);
        float v = __ldcs(&aval[i]);
        if (active) acc = ffma2(dup2(v), ldg64cg(S2b + (size_t)c * 160), acc);
        i++;
    }
    for (; i + 3 < e; i += 4) {
        int4   c4 = __ldcs((const int4*)&acol[i]);
        float4 v4 = __ldcs((const float4*)&aval[i]);
        if (active) {
            unsigned long long d0 = ldg64cg(S2b + (size_t)c4.x * 160);
            unsigned long long d1 = ldg64cg(S2b + (size_t)c4.y * 160);
            unsigned long long d2 = ldg64cg(S2b + (size_t)c4.z * 160);
            unsigned long long d3 = ldg64cg(S2b + (size_t)c4.w * 160);
            acc = ffma2(dup2(v4.x), d0, acc);
            acc = ffma2(dup2(v4.y), d1, acc);
            acc = ffma2(dup2(v4.z), d2, acc);
            acc = ffma2(dup2(v4.w), d3, acc);
        }
    }
    for (; i < e; i++) {
        int   c = __ldcs(&acol[i]);
        float v = __ldcs(&aval[i]);
        if (active) acc = ffma2(dup2(v), ldg64cg(S2b + (size_t)c * 160), acc);
    }

    float2 av = unpack2(acc);
    if (active) {
        float2 bb = *(const float2*)&b2[2 * lane];
        av.x += bb.x;
        av.y += bb.y;
    }

    float m = active ? fmaxf(av.x, av.y) : -INFINITY;
#pragma unroll
    for (int off = 16; off > 0; off >>= 1)
        m = fmaxf(m, __shfl_xor_sync(0xFFFFFFFFu, m, off));

    float se = active ? (expf(av.x - m) + expf(av.y - m)) : 0.f;
#pragma unroll
    for (int off = 16; off > 0; off >>= 1)
        se += __shfl_xor_sync(0xFFFFFFFFu, se, off);

    float lse = m + logf(se);
    if (active) {
        out[(size_t)warp * NCLASS + 2 * lane]     = av.x - lse;
        out[(size_t)warp * NCLASS + 2 * lane + 1] = av.y - lse;
    }
}

// ---------------- launch ----------------
extern "C" void kernel_launch(void* const* d_in, const int* in_sizes, int n_in,
                              void* d_out, int out_size) {
    const float* x    = (const float*)d_in[0];
    const int*   arow = (const int*)  d_in[1];
    const int*   acol = (const int*)  d_in[2];
    const float* aval = (const float*)d_in[3];
    // d_in[4] = i (unused)
    const float* W1 = (const float*)d_in[5];
    const float* b1 = (const float*)d_in[6];
    const float* W2 = (const float*)d_in[7];
    const float* b2 = (const float*)d_in[8];
    float* out = (float*)d_out;

    build_rowptr_kernel<<<(NN + 1 + 255) / 256, 256>>>(arow);
    w1bf16_kernel<<<(NFEAT * NHID + 255) / 256, 256>>>(W1);
    gemm1_bf16_kernel<<<(NN + 127) / 128, 256>>>(x);
    spmm1_kernel<<<(NN * 32 + 255) / 256, 256>>>(acol, aval, b1);
    gemm2_kernel<<<(NN + G2_BM - 1) / G2_BM, 256>>>(W2);
    spmm2_lsm_kernel<<<(NN * 32 + 255) / 256, 256>>>(acol, aval, b2, out);
}

// round 12
// speedup vs baseline: 1.2460x; 1.0121x over previous
#include <cuda_runtime.h>
#include <math.h>
#include <cstdint>

#define NN    100000
#define EE    3200000
#define NFEAT 256
#define NHID  128
#define NCLASS 40

// ---------------- scratch ----------------
__device__ __align__(16) float g_s1[NN * NHID];     // x @ W1 (51.2 MB)
__device__ __align__(16) float g_h [NN * NHID];     // relu(A@s1 + b1) (51.2 MB)
__device__ __align__(16) float g_s2[NN * NCLASS];   // h @ W2 (16 MB)
__device__ int g_rowptr[NN + 1];
// W1 bf16 hi/lo fragment image for m16n8k16: [c16(16)][ct(16)][h(2)][lane(32)][reg(2)] u32
__device__ __align__(16) uint32_t g_Bbf[32768];     // 128 KB

// ---------------- f32x2 packed helpers ----------------
__device__ __forceinline__ unsigned long long ffma2(unsigned long long a,
                                                    unsigned long long b,
                                                    unsigned long long c) {
    unsigned long long d;
    asm("fma.rn.f32x2 %0, %1, %2, %3;" : "=l"(d) : "l"(a), "l"(b), "l"(c));
    return d;
}
__device__ __forceinline__ unsigned long long dup2(float a) {
    unsigned long long d;
    asm("mov.b64 %0, {%1, %1};" : "=l"(d) : "f"(a));
    return d;
}
__device__ __forceinline__ float2 unpack2(unsigned long long v) {
    float2 f;
    asm("mov.b64 {%0, %1}, %2;" : "=f"(f.x), "=f"(f.y) : "l"(v));
    return f;
}
__device__ __forceinline__ unsigned long long ldg64cg(const void* p) {
    unsigned long long v;
    asm volatile("ld.global.cg.b64 %0, [%1];" : "=l"(v) : "l"(p));
    return v;
}
__device__ __forceinline__ void ldg128cg(const void* p, unsigned long long& a,
                                         unsigned long long& b) {
    asm volatile("ld.global.cg.v2.u64 {%0, %1}, [%2];" : "=l"(a), "=l"(b) : "l"(p));
}

// ---------------- cp.async helpers ----------------
__device__ __forceinline__ void cpa16(unsigned dst, const void* src, bool pred) {
    int sz = pred ? 16 : 0;
    asm volatile("cp.async.ca.shared.global [%0], [%1], 16, %2;\n"
                 :: "r"(dst), "l"(src), "r"(sz));
}
__device__ __forceinline__ void cpa_commit() { asm volatile("cp.async.commit_group;\n"); }
__device__ __forceinline__ void cpa_wait1()  { asm volatile("cp.async.wait_group 1;\n"); }
__device__ __forceinline__ void cpa_wait0()  { asm volatile("cp.async.wait_group 0;\n"); }

// ---------------- bf16 helpers ----------------
__device__ __forceinline__ uint32_t pack2bf(float2 v) {      // low16=bf16(v.x), high16=bf16(v.y)
    uint32_t d;
    asm("cvt.rn.bf16x2.f32 %0, %1, %2;" : "=r"(d) : "f"(v.y), "f"(v.x));
    return d;
}
__device__ __forceinline__ uint32_t pack2bf_lo(float2 v, uint32_t h) {
    float fx = __uint_as_float(h << 16);
    float fy = __uint_as_float(h & 0xFFFF0000u);
    float2 r = make_float2(v.x - fx, v.y - fy);
    return pack2bf(r);
}
#define MMA_BF16(d, a0, a1, a2, a3, b0, b1)                                      \
    asm volatile("mma.sync.aligned.m16n8k16.row.col.f32.bf16.bf16.f32 "         \
        "{%0,%1,%2,%3}, {%4,%5,%6,%7}, {%8,%9}, {%0,%1,%2,%3};"                 \
        : "+f"((d)[0]), "+f"((d)[1]), "+f"((d)[2]), "+f"((d)[3])                \
        : "r"(a0), "r"(a1), "r"(a2), "r"(a3), "r"(b0), "r"(b1))

// ---------------- CSR row_ptr ----------------
__global__ void build_rowptr_kernel(const int* __restrict__ arow) {
    int r = blockIdx.x * blockDim.x + threadIdx.x;
    if (r > NN) return;
    int lo = 0, hi = EE;
    while (lo < hi) {
        int mid = (lo + hi) >> 1;
        if (arow[mid] < r) lo = mid + 1; else hi = mid;
    }
    g_rowptr[r] = lo;
}

// ---------------- W1 -> bf16 hi/lo fragment image (m16n8k16, col-major B) ----------------
__global__ void w1bf16_kernel(const float* __restrict__ W1) {
    int idx = blockIdx.x * blockDim.x + threadIdx.x;
    if (idx >= NFEAT * NHID) return;
    int k = idx >> 7, n = idx & 127;
    float w = W1[idx];
    uint32_t hp = pack2bf(make_float2(w, 0.f));
    unsigned short hi16 = (unsigned short)(hp & 0xFFFFu);
    float fh = __uint_as_float((uint32_t)hi16 << 16);
    uint32_t lp = pack2bf(make_float2(w - fh, 0.f));
    unsigned short lo16 = (unsigned short)(lp & 0xFFFFu);

    int c16 = k >> 4, kk = k & 15;
    int ct = n >> 3, gid = n & 7;
    int reg = kk >> 3;
    int tig = (kk & 7) >> 1;
    int pos = kk & 1;
    int lane = gid * 4 + tig;
    int base16 = ((((c16 * 16 + ct) * 2 + 0) * 32 + lane) * 2 + reg) * 2 + pos;
    unsigned short* B16 = (unsigned short*)g_Bbf;
    B16[base16]       = hi16;     // h = 0
    B16[base16 + 128] = lo16;     // h = 1
}

// ---------------- GEMM1 (mma.sync bf16 hi/lo): g_s1 = X @ W1 ----------------
__global__ void __launch_bounds__(256) gemm1_bf16_kernel(const float* __restrict__ X) {
    __shared__ __align__(16) uint32_t sB[2][4096];   // 2 x 16KB

    const int tid  = threadIdx.x;
    const int lane = tid & 31;
    const int warp = tid >> 5;
    const int wrow = (warp >> 1) * 32;
    const int wcol = (warp & 1) * 64;
    const int row0 = blockIdx.x * 128;
    const int gid  = lane >> 2;
    const int tig  = lane & 3;
    const int ctb  = wcol >> 3;

    unsigned sb_addr = (unsigned)__cvta_generic_to_shared(&sB[0][0]);

    int rowi[2][2];
    bool rokg[2][2];
#pragma unroll
    for (int r = 0; r < 2; r++)
#pragma unroll
        for (int p = 0; p < 2; p++) {
            rowi[r][p] = row0 + wrow + r * 16 + gid + p * 8;
            rokg[r][p] = rowi[r][p] < NN;
        }

    float acc[2][8][4];
#pragma unroll
    for (int r = 0; r < 2; r++)
#pragma unroll
        for (int c = 0; c < 8; c++)
#pragma unroll
            for (int j = 0; j < 4; j++) acc[r][c][j] = 0.f;

#define G1_PREFETCH(stage, s)                                                    \
    do {                                                                         \
        _Pragma("unroll")                                                        \
        for (int j = 0; j < 4; j++) {                                            \
            int off = (j * 256 + tid) * 16;                                      \
            cpa16(sb_addr + (stage) * 16384 + off,                               \
                  (const char*)g_Bbf + (s) * 16384 + off, true);                 \
        }                                                                        \
        cpa_commit();                                                            \
    } while (0)

    G1_PREFETCH(0, 0);

    for (int s = 0; s < 8; s++) {
        if (s + 1 < 8) { G1_PREFETCH((s + 1) & 1, s + 1); cpa_wait1(); }
        else           { cpa_wait0(); }
        __syncthreads();

        float2 src[2][2][2][2];   // [sub][rt][rowpair][kpair]
#pragma unroll
        for (int sub = 0; sub < 2; sub++)
#pragma unroll
            for (int r = 0; r < 2; r++)
#pragma unroll
                for (int p = 0; p < 2; p++)
#pragma unroll
                    for (int q = 0; q < 2; q++) {
                        int kidx = s * 32 + sub * 16 + tig * 2 + q * 8;
                        src[sub][r][p][q] = rokg[r][p]
                            ? __ldg((const float2*)&X[(size_t)rowi[r][p] * NFEAT + kidx])
                            : make_float2(0.f, 0.f);
                    }

        const uint2* Bst = (const uint2*)&sB[s & 1][0];
#pragma unroll
        for (int sub = 0; sub < 2; sub++) {
            uint32_t ah[2][4], al[2][4];
#pragma unroll
            for (int r = 0; r < 2; r++) {
                ah[r][0] = pack2bf(src[sub][r][0][0]);
                ah[r][1] = pack2bf(src[sub][r][1][0]);
                ah[r][2] = pack2bf(src[sub][r][0][1]);
                ah[r][3] = pack2bf(src[sub][r][1][1]);
                al[r][0] = pack2bf_lo(src[sub][r][0][0], ah[r][0]);
                al[r][1] = pack2bf_lo(src[sub][r][1][0], ah[r][1]);
                al[r][2] = pack2bf_lo(src[sub][r][0][1], ah[r][2]);
                al[r][3] = pack2bf_lo(src[sub][r][1][1], ah[r][3]);
            }
#pragma unroll
            for (int c = 0; c < 8; c++) {
                int ctg = ctb + c;
                uint2 bhi = Bst[sub * 1024 + (ctg * 2 + 0) * 32 + lane];
                uint2 blo = Bst[sub * 1024 + (ctg * 2 + 1) * 32 + lane];
#pragma unroll
                for (int r = 0; r < 2; r++) {
                    MMA_BF16(acc[r][c], ah[r][0], ah[r][1], ah[r][2], ah[r][3], bhi.x, bhi.y);
                    MMA_BF16(acc[r][c], ah[r][0], ah[r][1], ah[r][2], ah[r][3], blo.x, blo.y);
                    MMA_BF16(acc[r][c], al[r][0], al[r][1], al[r][2], al[r][3], bhi.x, bhi.y);
                }
            }
        }
        __syncthreads();
    }

#pragma unroll
    for (int r = 0; r < 2; r++) {
#pragma unroll
        for (int c = 0; c < 8; c++) {
            int col = wcol + c * 8 + tig * 2;
            if (rokg[r][0])
                *(float2*)&g_s1[(size_t)rowi[r][0] * NHID + col] =
                    make_float2(acc[r][c][0], acc[r][c][1]);
            if (rokg[r][1])
                *(float2*)&g_s1[(size_t)rowi[r][1] * NHID + col] =
                    make_float2(acc[r][c][2], acc[r][c][3]);
        }
    }
#undef G1_PREFETCH
}

// ---------------- SpMM1 + bias + ReLU (warp/row, f32x2 accum, 16B gathers) ----------------
__global__ void spmm1_kernel(const int* __restrict__ acol, const float* __restrict__ aval,
                             const float* __restrict__ b1) {
    int warp = (blockIdx.x * blockDim.x + threadIdx.x) >> 5;
    int lane = threadIdx.x & 31;
    if (warp >= NN) return;

    int s = g_rowptr[warp];
    int e = g_rowptr[warp + 1];

    const char* S1b = (const char*)g_s1 + (size_t)lane * 16;
    unsigned long long a01 = 0ull, a23 = 0ull;

    int i = s;
    if ((i & 1) && i < e) {
        int   c = __ldcs(&acol[i]);
        float v = __ldcs(&aval[i]);
        unsigned long long d0, d1;
        ldg128cg(S1b + (size_t)c * 512, d0, d1);
        unsigned long long vv = dup2(v);
        a01 = ffma2(vv, d0, a01);
        a23 = ffma2(vv, d1, a23);
        i++;
    }
    for (; i + 1 < e; i += 2) {
        int2   c2 = __ldcs((const int2*)&acol[i]);
        float2 v2 = __ldcs((const float2*)&aval[i]);
        unsigned long long d0, d1, e0, e1;
        ldg128cg(S1b + (size_t)c2.x * 512, d0, d1);
        ldg128cg(S1b + (size_t)c2.y * 512, e0, e1);
        unsigned long long vx = dup2(v2.x), vy = dup2(v2.y);
        a01 = ffma2(vx, d0, a01);
        a23 = ffma2(vx, d1, a23);
        a01 = ffma2(vy, e0, a01);
        a23 = ffma2(vy, e1, a23);
    }
    if (i < e) {
        int   c = __ldcs(&acol[i]);
        float v = __ldcs(&aval[i]);
        unsigned long long d0, d1;
        ldg128cg(S1b + (size_t)c * 512, d0, d1);
        unsigned long long vv = dup2(v);
        a01 = ffma2(vv, d0, a01);
        a23 = ffma2(vv, d1, a23);
    }

    float2 p01 = unpack2(a01), p23 = unpack2(a23);
    float4 b = ((const float4*)b1)[lane];
    float4 r;
    r.x = fmaxf(p01.x + b.x, 0.f);
    r.y = fmaxf(p01.y + b.y, 0.f);
    r.z = fmaxf(p23.x + b.z, 0.f);
    r.w = fmaxf(p23.y + b.w, 0.f);
    ((float4*)g_h)[(size_t)warp * 32 + lane] = r;
}

// ---------------- GEMM2: s2 = h @ W2 (BM=256, BK=8, 2-stage cp.async) ----------------
#define G2_BM 256
#define G2_BK 8
#define G2_HS 12
#define G2_NT (NHID / G2_BK)     // 16
__global__ void __launch_bounds__(256) gemm2_kernel(const float* __restrict__ W2) {
    __shared__ float  Hs[2][G2_BM * G2_HS];
    __shared__ float2 Wp[NHID * 20];

    const int tid = threadIdx.x;
    const int pg  = tid & 3;
    const int rg  = tid >> 2;
    const int row0 = blockIdx.x * G2_BM;

    for (int j = tid; j < NHID * 20; j += 256) {
        int k = j / 20, p = j % 20;
        Wp[j] = *(const float2*)&W2[k * NCLASS + 2 * p];
    }

    unsigned hsb = (unsigned)__cvta_generic_to_shared(&Hs[0][0]);

#define G2_PREFETCH(stage, k0)                                                     \
    do {                                                                           \
        _Pragma("unroll")                                                          \
        for (int j = 0; j < 2; j++) {                                              \
            int fi = j * 256 + tid;                                                \
            int r  = fi >> 1;                                                      \
            int c4 = (fi & 1) * 4;                                                 \
            int grow = row0 + r;                                                   \
            unsigned dst = hsb + (stage) * (G2_BM * G2_HS * 4) + (r * G2_HS + c4) * 4; \
            cpa16(dst, &g_h[(size_t)grow * NHID + (k0) + c4], grow < NN);          \
        }                                                                          \
        cpa_commit();                                                              \
    } while (0)

    G2_PREFETCH(0, 0);

    unsigned long long acc[4][5];
#pragma unroll
    for (int i = 0; i < 4; i++)
#pragma unroll
        for (int j = 0; j < 5; j++) acc[i][j] = 0ull;

    for (int t = 0; t < G2_NT; t++) {
        if (t + 1 < G2_NT) {
            G2_PREFETCH((t + 1) & 1, (t + 1) * G2_BK);
            cpa_wait1();
        } else {
            cpa_wait0();
        }
        __syncthreads();

        const int st = t & 1;
        const int kbase = t * G2_BK;
#pragma unroll
        for (int kk = 0; kk < G2_BK; kk++) {
            unsigned long long hd[4];
#pragma unroll
            for (int i = 0; i < 4; i++)
                hd[i] = dup2(Hs[st][(rg + 64 * i) * G2_HS + kk]);
            unsigned long long wv[5];
#pragma unroll
            for (int j = 0; j < 5; j++)
                wv[j] = *(const unsigned long long*)&Wp[(kbase + kk) * 20 + pg * 5 + j];
#pragma unroll
            for (int i = 0; i < 4; i++)
#pragma unroll
                for (int j = 0; j < 5; j++)
                    acc[i][j] = ffma2(hd[i], wv[j], acc[i][j]);
        }
        __syncthreads();
    }

#pragma unroll
    for (int i = 0; i < 4; i++) {
        int grow = row0 + rg + 64 * i;
        if (grow < NN) {
#pragma unroll
            for (int j = 0; j < 5; j++) {
                float2 v = unpack2(acc[i][j]);
                *(float2*)&g_s2[(size_t)grow * NCLASS + 2 * (pg * 5 + j)] = v;
            }
        }
    }
#undef G2_PREFETCH
}

// ---------------- SpMM2 + bias + log_softmax ----------------
// 3 edges in flight per warp: lanes 0-29 = slot(lane/10) x seg(lane%10); each lane
// gathers float4 (classes 4*seg..+3) of its slot's edge row. Slot-reduce via shfl,
// lanes 0-9 finish with bias + warp log_softmax.
__global__ void spmm2_lsm_kernel(const int* __restrict__ acol, const float* __restrict__ aval,
                                 const float* __restrict__ b2, float* __restrict__ out) {
    int warp = (blockIdx.x * blockDim.x + threadIdx.x) >> 5;
    int lane = threadIdx.x & 31;
    if (warp >= NN) return;

    int s = g_rowptr[warp];
    int e = g_rowptr[warp + 1];

    const int slot = lane / 10;          // 0,1,2 (3 = lanes 30,31, inactive)
    const int seg  = lane - slot * 10;   // 0..9
    const bool lact = lane < 30;

    const char* S2b = (const char*)g_s2 + (size_t)seg * 16;
    unsigned long long acc0 = 0ull, acc1 = 0ull;

    for (int i = s; i < e; i += 3) {
        int ei = i + slot;
        bool ok = lact && (ei < e);
        int   c = 0;
        float v = 0.f;
        if (ok) {
            c = __ldcs(&acol[ei]);
            v = __ldcs(&aval[ei]);
        }
        unsigned long long d0 = 0ull, d1 = 0ull;
        if (ok) ldg128cg(S2b + (size_t)c * 160, d0, d1);
        unsigned long long vv = dup2(v);
        acc0 = ffma2(vv, d0, acc0);
        acc1 = ffma2(vv, d1, acc1);
    }

    // slot reduction: lanes 0..9 += lanes +10, +20
    float2 a0 = unpack2(acc0), a1 = unpack2(acc1);
    float vals[4] = {a0.x, a0.y, a1.x, a1.y};
#pragma unroll
    for (int j = 0; j < 4; j++) {
        float v10 = __shfl_down_sync(0xFFFFFFFFu, vals[j], 10);
        float v20 = __shfl_down_sync(0xFFFFFFFFu, vals[j], 20);
        vals[j] = vals[j] + v10 + v20;
    }

    bool outl = lane < 10;
    if (outl) {
        float4 bb = __ldg((const float4*)&b2[4 * seg]);
        vals[0] += bb.x; vals[1] += bb.y; vals[2] += bb.z; vals[3] += bb.w;
    }

    float m = outl ? fmaxf(fmaxf(vals[0], vals[1]), fmaxf(vals[2], vals[3])) : -INFINITY;
#pragma unroll
    for (int off = 16; off > 0; off >>= 1)
        m = fmaxf(m, __shfl_xor_sync(0xFFFFFFFFu, m, off));

    float se = outl ? (expf(vals[0] - m) + expf(vals[1] - m) +
                       expf(vals[2] - m) + expf(vals[3] - m)) : 0.f;
#pragma unroll
    for (int off = 16; off > 0; off >>= 1)
        se += __shfl_xor_sync(0xFFFFFFFFu, se, off);

    float lse = m + logf(se);
    if (outl) {
        float4 o;
        o.x = vals[0] - lse; o.y = vals[1] - lse;
        o.z = vals[2] - lse; o.w = vals[3] - lse;
        *(float4*)&out[(size_t)warp * NCLASS + 4 * seg] = o;
    }
}

// ---------------- launch ----------------
extern "C" void kernel_launch(void* const* d_in, const int* in_sizes, int n_in,
                              void* d_out, int out_size) {
    const float* x    = (const float*)d_in[0];
    const int*   arow = (const int*)  d_in[1];
    const int*   acol = (const int*)  d_in[2];
    const float* aval = (const float*)d_in[3];
    // d_in[4] = i (unused)
    const float* W1 = (const float*)d_in[5];
    const float* b1 = (const float*)d_in[6];
    const float* W2 = (const float*)d_in[7];
    const float* b2 = (const float*)d_in[8];
    float* out = (float*)d_out;

    build_rowptr_kernel<<<(NN + 1 + 255) / 256, 256>>>(arow);
    w1bf16_kernel<<<(NFEAT * NHID + 255) / 256, 256>>>(W1);
    gemm1_bf16_kernel<<<(NN + 127) / 128, 256>>>(x);
    spmm1_kernel<<<(NN * 32 + 255) / 256, 256>>>(acol, aval, b1);
    gemm2_kernel<<<(NN + G2_BM - 1) / G2_BM, 256>>>(W2);
    spmm2_lsm_kernel<<<(NN * 32 + 255) / 256, 256>>>(acol, aval, b2, out);
}

// round 13
// speedup vs baseline: 1.2498x; 1.0030x over previous
#include <cuda_runtime.h>
#include <math.h>
#include <cstdint>

#define NN    100000
#define EE    3200000
#define NFEAT 256
#define NHID  128
#define NCLASS 40

// ---------------- scratch ----------------
__device__ __align__(16) float g_s1[NN * NHID];     // x @ W1 (51.2 MB)
__device__ __align__(16) float g_h [NN * NHID];     // relu(A@s1 + b1) (51.2 MB)
__device__ __align__(16) float g_s2[NN * NCLASS];   // h @ W2 (16 MB)
__device__ int g_rowptr[NN + 1];
// W1 bf16 hi/lo fragment image for m16n8k16: [c16(16)][ct(16)][h(2)][lane(32)][reg(2)] u32
__device__ __align__(16) uint32_t g_Bbf[32768];     // 128 KB

// ---------------- f32x2 packed helpers ----------------
__device__ __forceinline__ unsigned long long ffma2(unsigned long long a,
                                                    unsigned long long b,
                                                    unsigned long long c) {
    unsigned long long d;
    asm("fma.rn.f32x2 %0, %1, %2, %3;" : "=l"(d) : "l"(a), "l"(b), "l"(c));
    return d;
}
__device__ __forceinline__ unsigned long long dup2(float a) {
    unsigned long long d;
    asm("mov.b64 %0, {%1, %1};" : "=l"(d) : "f"(a));
    return d;
}
__device__ __forceinline__ float2 unpack2(unsigned long long v) {
    float2 f;
    asm("mov.b64 {%0, %1}, %2;" : "=f"(f.x), "=f"(f.y) : "l"(v));
    return f;
}
__device__ __forceinline__ unsigned long long ldg64cg(const void* p) {
    unsigned long long v;
    asm volatile("ld.global.cg.b64 %0, [%1];" : "=l"(v) : "l"(p));
    return v;
}
__device__ __forceinline__ void ldg128cg(const void* p, unsigned long long& a,
                                         unsigned long long& b) {
    asm volatile("ld.global.cg.v2.u64 {%0, %1}, [%2];" : "=l"(a), "=l"(b) : "l"(p));
}

// ---------------- cp.async helpers ----------------
__device__ __forceinline__ void cpa16(unsigned dst, const void* src, bool pred) {
    int sz = pred ? 16 : 0;
    asm volatile("cp.async.ca.shared.global [%0], [%1], 16, %2;\n"
                 :: "r"(dst), "l"(src), "r"(sz));
}
__device__ __forceinline__ void cpa_commit() { asm volatile("cp.async.commit_group;\n"); }
__device__ __forceinline__ void cpa_wait1()  { asm volatile("cp.async.wait_group 1;\n"); }
__device__ __forceinline__ void cpa_wait0()  { asm volatile("cp.async.wait_group 0;\n"); }

// ---------------- bf16 helpers ----------------
__device__ __forceinline__ uint32_t pack2bf(float2 v) {      // low16=bf16(v.x), high16=bf16(v.y)
    uint32_t d;
    asm("cvt.rn.bf16x2.f32 %0, %1, %2;" : "=r"(d) : "f"(v.y), "f"(v.x));
    return d;
}
__device__ __forceinline__ uint32_t pack2bf_lo(float2 v, uint32_t h) {
    float fx = __uint_as_float(h << 16);
    float fy = __uint_as_float(h & 0xFFFF0000u);
    float2 r = make_float2(v.x - fx, v.y - fy);
    return pack2bf(r);
}
#define MMA_BF16(d, a0, a1, a2, a3, b0, b1)                                      \
    asm volatile("mma.sync.aligned.m16n8k16.row.col.f32.bf16.bf16.f32 "         \
        "{%0,%1,%2,%3}, {%4,%5,%6,%7}, {%8,%9}, {%0,%1,%2,%3};"                 \
        : "+f"((d)[0]), "+f"((d)[1]), "+f"((d)[2]), "+f"((d)[3])                \
        : "r"(a0), "r"(a1), "r"(a2), "r"(a3), "r"(b0), "r"(b1))

// ---------------- CSR row_ptr ----------------
__global__ void build_rowptr_kernel(const int* __restrict__ arow) {
    int r = blockIdx.x * blockDim.x + threadIdx.x;
    if (r > NN) return;
    int lo = 0, hi = EE;
    while (lo < hi) {
        int mid = (lo + hi) >> 1;
        if (arow[mid] < r) lo = mid + 1; else hi = mid;
    }
    g_rowptr[r] = lo;
}

// ---------------- W1 -> bf16 hi/lo fragment image (m16n8k16, col-major B) ----------------
__global__ void w1bf16_kernel(const float* __restrict__ W1) {
    int idx = blockIdx.x * blockDim.x + threadIdx.x;
    if (idx >= NFEAT * NHID) return;
    int k = idx >> 7, n = idx & 127;
    float w = W1[idx];
    uint32_t hp = pack2bf(make_float2(w, 0.f));
    unsigned short hi16 = (unsigned short)(hp & 0xFFFFu);
    float fh = __uint_as_float((uint32_t)hi16 << 16);
    uint32_t lp = pack2bf(make_float2(w - fh, 0.f));
    unsigned short lo16 = (unsigned short)(lp & 0xFFFFu);

    int c16 = k >> 4, kk = k & 15;
    int ct = n >> 3, gid = n & 7;
    int reg = kk >> 3;
    int tig = (kk & 7) >> 1;
    int pos = kk & 1;
    int lane = gid * 4 + tig;
    int base16 = ((((c16 * 16 + ct) * 2 + 0) * 32 + lane) * 2 + reg) * 2 + pos;
    unsigned short* B16 = (unsigned short*)g_Bbf;
    B16[base16]       = hi16;     // h = 0
    B16[base16 + 128] = lo16;     // h = 1
}

// ---------------- GEMM1 (mma.sync bf16 hi/lo): g_s1 = X @ W1 ----------------
// 128x128 tile/CTA, 512 threads, 16 warps in 8x2 (16 rows x 64 cols each).
// A fragments double-buffered in regs (loaded a full stage ahead); B image
// cp.async double-buffered. 3 passes: Ahi*Bhi + Ahi*Blo + Alo*Bhi.
__global__ void __launch_bounds__(512) gemm1_bf16_kernel(const float* __restrict__ X) {
    __shared__ __align__(16) uint32_t sB[2][4096];   // 2 x 16KB

    const int tid  = threadIdx.x;
    const int lane = tid & 31;
    const int warp = tid >> 5;
    const int wrow = (warp >> 1) * 16;
    const int wcol = (warp & 1) * 64;
    const int row0 = blockIdx.x * 128;
    const int gid  = lane >> 2;
    const int tig  = lane & 3;
    const int ctb  = wcol >> 3;

    unsigned sb_addr = (unsigned)__cvta_generic_to_shared(&sB[0][0]);

    int rowi[2];
    bool rokg[2];
#pragma unroll
    for (int p = 0; p < 2; p++) {
        rowi[p] = row0 + wrow + gid + p * 8;
        rokg[p] = rowi[p] < NN;
    }

    float acc[8][4];
#pragma unroll
    for (int c = 0; c < 8; c++)
#pragma unroll
        for (int j = 0; j < 4; j++) acc[c][j] = 0.f;

#define G1_PREFETCH(stage, s)                                                    \
    do {                                                                         \
        _Pragma("unroll")                                                        \
        for (int j = 0; j < 2; j++) {                                            \
            int off = (j * 512 + tid) * 16;                                      \
            cpa16(sb_addr + (stage) * 16384 + off,                               \
                  (const char*)g_Bbf + (s) * 16384 + off, true);                 \
        }                                                                        \
        cpa_commit();                                                            \
    } while (0)

#define G1_LOAD_A(dst, s_)                                                       \
    do {                                                                         \
        _Pragma("unroll")                                                        \
        for (int sub = 0; sub < 2; sub++)                                        \
            _Pragma("unroll")                                                    \
            for (int p = 0; p < 2; p++)                                          \
                _Pragma("unroll")                                                \
                for (int q = 0; q < 2; q++) {                                    \
                    int kidx = (s_) * 32 + sub * 16 + tig * 2 + q * 8;           \
                    (dst)[sub][p][q] = rokg[p]                                   \
                        ? __ldg((const float2*)&X[(size_t)rowi[p] * NFEAT + kidx]) \
                        : make_float2(0.f, 0.f);                                 \
                }                                                                \
    } while (0)

    float2 srcA[2][2][2], srcB[2][2][2];
    G1_LOAD_A(srcA, 0);
    G1_PREFETCH(0, 0);

    for (int s = 0; s < 8; s++) {
        // kick off next stage's B prefetch + A loads BEFORE consuming this stage
        if (s + 1 < 8) {
            G1_PREFETCH((s + 1) & 1, s + 1);
            if (s & 1) G1_LOAD_A(srcA, s + 1); else G1_LOAD_A(srcB, s + 1);
            cpa_wait1();
        } else {
            cpa_wait0();
        }
        __syncthreads();

        float2 (*cur)[2][2] = (s & 1) ? srcB : srcA;
        const uint2* Bst = (const uint2*)&sB[s & 1][0];
#pragma unroll
        for (int sub = 0; sub < 2; sub++) {
            uint32_t ah[4], al[4];
            ah[0] = pack2bf(cur[sub][0][0]);
            ah[1] = pack2bf(cur[sub][1][0]);
            ah[2] = pack2bf(cur[sub][0][1]);
            ah[3] = pack2bf(cur[sub][1][1]);
            al[0] = pack2bf_lo(cur[sub][0][0], ah[0]);
            al[1] = pack2bf_lo(cur[sub][1][0], ah[1]);
            al[2] = pack2bf_lo(cur[sub][0][1], ah[2]);
            al[3] = pack2bf_lo(cur[sub][1][1], ah[3]);
#pragma unroll
            for (int c = 0; c < 8; c++) {
                int ctg = ctb + c;
                uint2 bhi = Bst[sub * 1024 + (ctg * 2 + 0) * 32 + lane];
                uint2 blo = Bst[sub * 1024 + (ctg * 2 + 1) * 32 + lane];
                MMA_BF16(acc[c], ah[0], ah[1], ah[2], ah[3], bhi.x, bhi.y);
                MMA_BF16(acc[c], ah[0], ah[1], ah[2], ah[3], blo.x, blo.y);
                MMA_BF16(acc[c], al[0], al[1], al[2], al[3], bhi.x, bhi.y);
            }
        }
        __syncthreads();
    }

#pragma unroll
    for (int c = 0; c < 8; c++) {
        int col = wcol + c * 8 + tig * 2;
        if (rokg[0])
            *(float2*)&g_s1[(size_t)rowi[0] * NHID + col] = make_float2(acc[c][0], acc[c][1]);
        if (rokg[1])
            *(float2*)&g_s1[(size_t)rowi[1] * NHID + col] = make_float2(acc[c][2], acc[c][3]);
    }
#undef G1_PREFETCH
#undef G1_LOAD_A
}

// ---------------- SpMM1 + bias + ReLU (warp/row, f32x2 accum, 16B gathers) ----------------
__global__ void spmm1_kernel(const int* __restrict__ acol, const float* __restrict__ aval,
                             const float* __restrict__ b1) {
    int warp = (blockIdx.x * blockDim.x + threadIdx.x) >> 5;
    int lane = threadIdx.x & 31;
    if (warp >= NN) return;

    int s = g_rowptr[warp];
    int e = g_rowptr[warp + 1];

    const char* S1b = (const char*)g_s1 + (size_t)lane * 16;
    unsigned long long a01 = 0ull, a23 = 0ull;

    int i = s;
    if ((i & 1) && i < e) {
        int   c = __ldcs(&acol[i]);
        float v = __ldcs(&aval[i]);
        unsigned long long d0, d1;
        ldg128cg(S1b + (size_t)c * 512, d0, d1);
        unsigned long long vv = dup2(v);
        a01 = ffma2(vv, d0, a01);
        a23 = ffma2(vv, d1, a23);
        i++;
    }
    for (; i + 1 < e; i += 2) {
        int2   c2 = __ldcs((const int2*)&acol[i]);
        float2 v2 = __ldcs((const float2*)&aval[i]);
        unsigned long long d0, d1, e0, e1;
        ldg128cg(S1b + (size_t)c2.x * 512, d0, d1);
        ldg128cg(S1b + (size_t)c2.y * 512, e0, e1);
        unsigned long long vx = dup2(v2.x), vy = dup2(v2.y);
        a01 = ffma2(vx, d0, a01);
        a23 = ffma2(vx, d1, a23);
        a01 = ffma2(vy, e0, a01);
        a23 = ffma2(vy, e1, a23);
    }
    if (i < e) {
        int   c = __ldcs(&acol[i]);
        float v = __ldcs(&aval[i]);
        unsigned long long d0, d1;
        ldg128cg(S1b + (size_t)c * 512, d0, d1);
        unsigned long long vv = dup2(v);
        a01 = ffma2(vv, d0, a01);
        a23 = ffma2(vv, d1, a23);
    }

    float2 p01 = unpack2(a01), p23 = unpack2(a23);
    float4 b = ((const float4*)b1)[lane];
    float4 r;
    r.x = fmaxf(p01.x + b.x, 0.f);
    r.y = fmaxf(p01.y + b.y, 0.f);
    r.z = fmaxf(p23.x + b.z, 0.f);
    r.w = fmaxf(p23.y + b.w, 0.f);
    ((float4*)g_h)[(size_t)warp * 32 + lane] = r;
}

// ---------------- GEMM2: s2 = h @ W2 (BM=256, BK=8, 2-stage cp.async) ----------------
#define G2_BM 256
#define G2_BK 8
#define G2_HS 12
#define G2_NT (NHID / G2_BK)     // 16
__global__ void __launch_bounds__(256) gemm2_kernel(const float* __restrict__ W2) {
    __shared__ float  Hs[2][G2_BM * G2_HS];
    __shared__ float2 Wp[NHID * 20];

    const int tid = threadIdx.x;
    const int pg  = tid & 3;
    const int rg  = tid >> 2;
    const int row0 = blockIdx.x * G2_BM;

    for (int j = tid; j < NHID * 20; j += 256) {
        int k = j / 20, p = j % 20;
        Wp[j] = *(const float2*)&W2[k * NCLASS + 2 * p];
    }

    unsigned hsb = (unsigned)__cvta_generic_to_shared(&Hs[0][0]);

#define G2_PREFETCH(stage, k0)                                                     \
    do {                                                                           \
        _Pragma("unroll")                                                          \
        for (int j = 0; j < 2; j++) {                                              \
            int fi = j * 256 + tid;                                                \
            int r  = fi >> 1;                                                      \
            int c4 = (fi & 1) * 4;                                                 \
            int grow = row0 + r;                                                   \
            unsigned dst = hsb + (stage) * (G2_BM * G2_HS * 4) + (r * G2_HS + c4) * 4; \
            cpa16(dst, &g_h[(size_t)grow * NHID + (k0) + c4], grow < NN);          \
        }                                                                          \
        cpa_commit();                                                              \
    } while (0)

    G2_PREFETCH(0, 0);

    unsigned long long acc[4][5];
#pragma unroll
    for (int i = 0; i < 4; i++)
#pragma unroll
        for (int j = 0; j < 5; j++) acc[i][j] = 0ull;

    for (int t = 0; t < G2_NT; t++) {
        if (t + 1 < G2_NT) {
            G2_PREFETCH((t + 1) & 1, (t + 1) * G2_BK);
            cpa_wait1();
        } else {
            cpa_wait0();
        }
        __syncthreads();

        const int st = t & 1;
        const int kbase = t * G2_BK;
#pragma unroll
        for (int kk = 0; kk < G2_BK; kk++) {
            unsigned long long hd[4];
#pragma unroll
            for (int i = 0; i < 4; i++)
                hd[i] = dup2(Hs[st][(rg + 64 * i) * G2_HS + kk]);
            unsigned long long wv[5];
#pragma unroll
            for (int j = 0; j < 5; j++)
                wv[j] = *(const unsigned long long*)&Wp[(kbase + kk) * 20 + pg * 5 + j];
#pragma unroll
            for (int i = 0; i < 4; i++)
#pragma unroll
                for (int j = 0; j < 5; j++)
                    acc[i][j] = ffma2(hd[i], wv[j], acc[i][j]);
        }
        __syncthreads();
    }

#pragma unroll
    for (int i = 0; i < 4; i++) {
        int grow = row0 + rg + 64 * i;
        if (grow < NN) {
#pragma unroll
            for (int j = 0; j < 5; j++) {
                float2 v = unpack2(acc[i][j]);
                *(float2*)&g_s2[(size_t)grow * NCLASS + 2 * (pg * 5 + j)] = v;
            }
        }
    }
#undef G2_PREFETCH
}

// ---------------- SpMM2 + bias + log_softmax ----------------
// 6 edges in flight per warp (3 slots x 2-deep unroll); lanes 0-29 active.
__global__ void spmm2_lsm_kernel(const int* __restrict__ acol, const float* __restrict__ aval,
                                 const float* __restrict__ b2, float* __restrict__ out) {
    int warp = (blockIdx.x * blockDim.x + threadIdx.x) >> 5;
    int lane = threadIdx.x & 31;
    if (warp >= NN) return;

    int s = g_rowptr[warp];
    int e = g_rowptr[warp + 1];

    const int slot = lane / 10;          // 0,1,2 (lanes 30,31 inactive)
    const int seg  = lane - slot * 10;   // 0..9
    const bool lact = lane < 30;

    const char* S2b = (const char*)g_s2 + (size_t)seg * 16;
    unsigned long long acc0 = 0ull, acc1 = 0ull;

    int i = s;
    for (; i + 5 < e; i += 6) {          // both edges guaranteed in range
        int ei0 = i + slot, ei1 = i + 3 + slot;
        int c0 = 0, c1 = 0;
        float v0 = 0.f, v1 = 0.f;
        unsigned long long d0a = 0ull, d1a = 0ull, d0b = 0ull, d1b = 0ull;
        if (lact) {
            c0 = __ldcs(&acol[ei0]);
            c1 = __ldcs(&acol[ei1]);
            v0 = __ldcs(&aval[ei0]);
            v1 = __ldcs(&aval[ei1]);
            ldg128cg(S2b + (size_t)c0 * 160, d0a, d1a);
            ldg128cg(S2b + (size_t)c1 * 160, d0b, d1b);
        }
        unsigned long long vv0 = dup2(v0), vv1 = dup2(v1);
        acc0 = ffma2(vv0, d0a, acc0);
        acc1 = ffma2(vv0, d1a, acc1);
        acc0 = ffma2(vv1, d0b, acc0);
        acc1 = ffma2(vv1, d1b, acc1);
    }
    for (; i < e; i += 3) {
        int ei = i + slot;
        bool ok = lact && (ei < e);
        int   c = 0;
        float v = 0.f;
        if (ok) {
            c = __ldcs(&acol[ei]);
            v = __ldcs(&aval[ei]);
        }
        unsigned long long d0 = 0ull, d1 = 0ull;
        if (ok) ldg128cg(S2b + (size_t)c * 160, d0, d1);
        unsigned long long vv = dup2(v);
        acc0 = ffma2(vv, d0, acc0);
        acc1 = ffma2(vv, d1, acc1);
    }

    // slot reduction: lanes 0..9 += lanes +10, +20
    float2 a0 = unpack2(acc0), a1 = unpack2(acc1);
    float vals[4] = {a0.x, a0.y, a1.x, a1.y};
#pragma unroll
    for (int j = 0; j < 4; j++) {
        float v10 = __shfl_down_sync(0xFFFFFFFFu, vals[j], 10);
        float v20 = __shfl_down_sync(0xFFFFFFFFu, vals[j], 20);
        vals[j] = vals[j] + v10 + v20;
    }

    bool outl = lane < 10;
    if (outl) {
        float4 bb = __ldg((const float4*)&b2[4 * seg]);
        vals[0] += bb.x; vals[1] += bb.y; vals[2] += bb.z; vals[3] += bb.w;
    }

    float m = outl ? fmaxf(fmaxf(vals[0], vals[1]), fmaxf(vals[2], vals[3])) : -INFINITY;
#pragma unroll
    for (int off = 16; off > 0; off >>= 1)
        m = fmaxf(m, __shfl_xor_sync(0xFFFFFFFFu, m, off));

    float se = outl ? (expf(vals[0] - m) + expf(vals[1] - m) +
                       expf(vals[2] - m) + expf(vals[3] - m)) : 0.f;
#pragma unroll
    for (int off = 16; off > 0; off >>= 1)
        se += __shfl_xor_sync(0xFFFFFFFFu, se, off);

    float lse = m + logf(se);
    if (outl) {
        float4 o;
        o.x = vals[0] - lse; o.y = vals[1] - lse;
        o.z = vals[2] - lse; o.w = vals[3] - lse;
        *(float4*)&out[(size_t)warp * NCLASS + 4 * seg] = o;
    }
}

// ---------------- launch ----------------
extern "C" void kernel_launch(void* const* d_in, const int* in_sizes, int n_in,
                              void* d_out, int out_size) {
    const float* x    = (const float*)d_in[0];
    const int*   arow = (const int*)  d_in[1];
    const int*   acol = (const int*)  d_in[2];
    const float* aval = (const float*)d_in[3];
    // d_in[4] = i (unused)
    const float* W1 = (const float*)d_in[5];
    const float* b1 = (const float*)d_in[6];
    const float* W2 = (const float*)d_in[7];
    const float* b2 = (const float*)d_in[8];
    float* out = (float*)d_out;

    build_rowptr_kernel<<<(NN + 1 + 255) / 256, 256>>>(arow);
    w1bf16_kernel<<<(NFEAT * NHID + 255) / 256, 256>>>(W1);
    gemm1_bf16_kernel<<<(NN + 127) / 128, 512>>>(x);
    spmm1_kernel<<<(NN * 32 + 255) / 256, 256>>>(acol, aval, b1);
    gemm2_kernel<<<(NN + G2_BM - 1) / G2_BM, 256>>>(W2);
    spmm2_lsm_kernel<<<(NN * 32 + 255) / 256, 256>>>(acol, aval, b2, out);
}

// round 14
// speedup vs baseline: 1.3527x; 1.0823x over previous
#include <cuda_runtime.h>
#include <math.h>
#include <cstdint>

#define NN    100000
#define EE    3200000
#define NFEAT 256
#define NHID  128
#define NCLASS 40

// ---------------- scratch ----------------
__device__ __align__(16) unsigned short g_s1h[NN * NHID];   // x @ W1, fp16 (25.6 MB)
__device__ __align__(16) unsigned short g_hh [NN * NHID];   // relu(A@s1+b1), fp16 (25.6 MB)
__device__ __align__(16) float g_s2[NN * NCLASS];           // h @ W2 (16 MB)
__device__ int g_rowptr[NN + 1];
// W1 bf16 hi/lo fragment image for m16n8k16
__device__ __align__(16) uint32_t g_Bbf[32768];             // 128 KB

// ---------------- f32x2 packed helpers ----------------
__device__ __forceinline__ unsigned long long ffma2(unsigned long long a,
                                                    unsigned long long b,
                                                    unsigned long long c) {
    unsigned long long d;
    asm("fma.rn.f32x2 %0, %1, %2, %3;" : "=l"(d) : "l"(a), "l"(b), "l"(c));
    return d;
}
__device__ __forceinline__ unsigned long long dup2(float a) {
    unsigned long long d;
    asm("mov.b64 %0, {%1, %1};" : "=l"(d) : "f"(a));
    return d;
}
__device__ __forceinline__ unsigned long long packf2(float2 f) {
    unsigned long long d;
    asm("mov.b64 %0, {%1, %2};" : "=l"(d) : "f"(f.x), "f"(f.y));
    return d;
}
__device__ __forceinline__ float2 unpack2(unsigned long long v) {
    float2 f;
    asm("mov.b64 {%0, %1}, %2;" : "=f"(f.x), "=f"(f.y) : "l"(v));
    return f;
}
__device__ __forceinline__ unsigned long long ldg64cg(const void* p) {
    unsigned long long v;
    asm volatile("ld.global.cg.b64 %0, [%1];" : "=l"(v) : "l"(p));
    return v;
}
__device__ __forceinline__ void ldg128cg(const void* p, unsigned long long& a,
                                         unsigned long long& b) {
    asm volatile("ld.global.cg.v2.u64 {%0, %1}, [%2];" : "=l"(a), "=l"(b) : "l"(p));
}

// ---------------- fp16 storage helpers ----------------
__device__ __forceinline__ uint32_t packf16(float2 v) {      // low16 = f16(v.x)
    uint32_t d;
    asm("cvt.rn.f16x2.f32 %0, %1, %2;" : "=r"(d) : "f"(v.y), "f"(v.x));
    return d;
}
__device__ __forceinline__ float2 unpackf16(uint32_t h) {
    float2 f;
    asm("{\n\t.reg .b16 lo, hi;\n\t"
        "mov.b32 {lo, hi}, %2;\n\t"
        "cvt.f32.f16 %0, lo;\n\t"
        "cvt.f32.f16 %1, hi;\n\t}"
        : "=f"(f.x), "=f"(f.y) : "r"(h));
    return f;
}

// ---------------- cp.async helpers ----------------
__device__ __forceinline__ void cpa16(unsigned dst, const void* src, bool pred) {
    int sz = pred ? 16 : 0;
    asm volatile("cp.async.ca.shared.global [%0], [%1], 16, %2;\n"
                 :: "r"(dst), "l"(src), "r"(sz));
}
__device__ __forceinline__ void cpa_commit() { asm volatile("cp.async.commit_group;\n"); }
__device__ __forceinline__ void cpa_wait1()  { asm volatile("cp.async.wait_group 1;\n"); }
__device__ __forceinline__ void cpa_wait0()  { asm volatile("cp.async.wait_group 0;\n"); }

// ---------------- bf16 helpers (gemm1 hi/lo split) ----------------
__device__ __forceinline__ uint32_t pack2bf(float2 v) {
    uint32_t d;
    asm("cvt.rn.bf16x2.f32 %0, %1, %2;" : "=r"(d) : "f"(v.y), "f"(v.x));
    return d;
}
__device__ __forceinline__ uint32_t pack2bf_lo(float2 v, uint32_t h) {
    float fx = __uint_as_float(h << 16);
    float fy = __uint_as_float(h & 0xFFFF0000u);
    float2 r = make_float2(v.x - fx, v.y - fy);
    return pack2bf(r);
}
#define MMA_BF16(d, a0, a1, a2, a3, b0, b1)                                      \
    asm volatile("mma.sync.aligned.m16n8k16.row.col.f32.bf16.bf16.f32 "         \
        "{%0,%1,%2,%3}, {%4,%5,%6,%7}, {%8,%9}, {%0,%1,%2,%3};"                 \
        : "+f"((d)[0]), "+f"((d)[1]), "+f"((d)[2]), "+f"((d)[3])                \
        : "r"(a0), "r"(a1), "r"(a2), "r"(a3), "r"(b0), "r"(b1))

// ---------------- CSR row_ptr ----------------
__global__ void build_rowptr_kernel(const int* __restrict__ arow) {
    int r = blockIdx.x * blockDim.x + threadIdx.x;
    if (r > NN) return;
    int lo = 0, hi = EE;
    while (lo < hi) {
        int mid = (lo + hi) >> 1;
        if (arow[mid] < r) lo = mid + 1; else hi = mid;
    }
    g_rowptr[r] = lo;
}

// ---------------- W1 -> bf16 hi/lo fragment image (m16n8k16, col-major B) ----------------
__global__ void w1bf16_kernel(const float* __restrict__ W1) {
    int idx = blockIdx.x * blockDim.x + threadIdx.x;
    if (idx >= NFEAT * NHID) return;
    int k = idx >> 7, n = idx & 127;
    float w = W1[idx];
    uint32_t hp = pack2bf(make_float2(w, 0.f));
    unsigned short hi16 = (unsigned short)(hp & 0xFFFFu);
    float fh = __uint_as_float((uint32_t)hi16 << 16);
    uint32_t lp = pack2bf(make_float2(w - fh, 0.f));
    unsigned short lo16 = (unsigned short)(lp & 0xFFFFu);

    int c16 = k >> 4, kk = k & 15;
    int ct = n >> 3, gid = n & 7;
    int reg = kk >> 3;
    int tig = (kk & 7) >> 1;
    int pos = kk & 1;
    int lane = gid * 4 + tig;
    int base16 = ((((c16 * 16 + ct) * 2 + 0) * 32 + lane) * 2 + reg) * 2 + pos;
    unsigned short* B16 = (unsigned short*)g_Bbf;
    B16[base16]       = hi16;     // h = 0
    B16[base16 + 128] = lo16;     // h = 1
}

// ---------------- GEMM1 (mma.sync bf16 hi/lo): g_s1h = fp16(X @ W1) ----------------
// 128x128 tile/CTA, 512 threads, 16 warps in 8x2 (16 rows x 64 cols each).
__global__ void __launch_bounds__(512) gemm1_bf16_kernel(const float* __restrict__ X) {
    __shared__ __align__(16) uint32_t sB[2][4096];   // 2 x 16KB

    const int tid  = threadIdx.x;
    const int lane = tid & 31;
    const int warp = tid >> 5;
    const int wrow = (warp >> 1) * 16;
    const int wcol = (warp & 1) * 64;
    const int row0 = blockIdx.x * 128;
    const int gid  = lane >> 2;
    const int tig  = lane & 3;
    const int ctb  = wcol >> 3;

    unsigned sb_addr = (unsigned)__cvta_generic_to_shared(&sB[0][0]);

    int rowi[2];
    bool rokg[2];
#pragma unroll
    for (int p = 0; p < 2; p++) {
        rowi[p] = row0 + wrow + gid + p * 8;
        rokg[p] = rowi[p] < NN;
    }

    float acc[8][4];
#pragma unroll
    for (int c = 0; c < 8; c++)
#pragma unroll
        for (int j = 0; j < 4; j++) acc[c][j] = 0.f;

#define G1_PREFETCH(stage, s)                                                    \
    do {                                                                         \
        _Pragma("unroll")                                                        \
        for (int j = 0; j < 2; j++) {                                            \
            int off = (j * 512 + tid) * 16;                                      \
            cpa16(sb_addr + (stage) * 16384 + off,                               \
                  (const char*)g_Bbf + (s) * 16384 + off, true);                 \
        }                                                                        \
        cpa_commit();                                                            \
    } while (0)

#define G1_LOAD_A(dst, s_)                                                       \
    do {                                                                         \
        _Pragma("unroll")                                                        \
        for (int sub = 0; sub < 2; sub++)                                        \
            _Pragma("unroll")                                                    \
            for (int p = 0; p < 2; p++)                                          \
                _Pragma("unroll")                                                \
                for (int q = 0; q < 2; q++) {                                    \
                    int kidx = (s_) * 32 + sub * 16 + tig * 2 + q * 8;           \
                    (dst)[sub][p][q] = rokg[p]                                   \
                        ? __ldg((const float2*)&X[(size_t)rowi[p] * NFEAT + kidx]) \
                        : make_float2(0.f, 0.f);                                 \
                }                                                                \
    } while (0)

    float2 srcA[2][2][2], srcB[2][2][2];
    G1_LOAD_A(srcA, 0);
    G1_PREFETCH(0, 0);

    for (int s = 0; s < 8; s++) {
        if (s + 1 < 8) {
            G1_PREFETCH((s + 1) & 1, s + 1);
            if (s & 1) G1_LOAD_A(srcA, s + 1); else G1_LOAD_A(srcB, s + 1);
            cpa_wait1();
        } else {
            cpa_wait0();
        }
        __syncthreads();

        float2 (*cur)[2][2] = (s & 1) ? srcB : srcA;
        const uint2* Bst = (const uint2*)&sB[s & 1][0];
#pragma unroll
        for (int sub = 0; sub < 2; sub++) {
            uint32_t ah[4], al[4];
            ah[0] = pack2bf(cur[sub][0][0]);
            ah[1] = pack2bf(cur[sub][1][0]);
            ah[2] = pack2bf(cur[sub][0][1]);
            ah[3] = pack2bf(cur[sub][1][1]);
            al[0] = pack2bf_lo(cur[sub][0][0], ah[0]);
            al[1] = pack2bf_lo(cur[sub][1][0], ah[1]);
            al[2] = pack2bf_lo(cur[sub][0][1], ah[2]);
            al[3] = pack2bf_lo(cur[sub][1][1], ah[3]);
#pragma unroll
            for (int c = 0; c < 8; c++) {
                int ctg = ctb + c;
                uint2 bhi = Bst[sub * 1024 + (ctg * 2 + 0) * 32 + lane];
                uint2 blo = Bst[sub * 1024 + (ctg * 2 + 1) * 32 + lane];
                MMA_BF16(acc[c], ah[0], ah[1], ah[2], ah[3], bhi.x, bhi.y);
                MMA_BF16(acc[c], ah[0], ah[1], ah[2], ah[3], blo.x, blo.y);
                MMA_BF16(acc[c], al[0], al[1], al[2], al[3], bhi.x, bhi.y);
            }
        }
        __syncthreads();
    }

    // store fp16
#pragma unroll
    for (int c = 0; c < 8; c++) {
        int col = wcol + c * 8 + tig * 2;
        if (rokg[0])
            *(uint32_t*)&g_s1h[(size_t)rowi[0] * NHID + col] =
                packf16(make_float2(acc[c][0], acc[c][1]));
        if (rokg[1])
            *(uint32_t*)&g_s1h[(size_t)rowi[1] * NHID + col] =
                packf16(make_float2(acc[c][2], acc[c][3]));
    }
#undef G1_PREFETCH
#undef G1_LOAD_A
}

// ---------------- SpMM1 + bias + ReLU (warp/row, fp16 gathers 8B/lane) ----------------
__global__ void spmm1_kernel(const int* __restrict__ acol, const float* __restrict__ aval,
                             const float* __restrict__ b1) {
    int warp = (blockIdx.x * blockDim.x + threadIdx.x) >> 5;
    int lane = threadIdx.x & 31;
    if (warp >= NN) return;

    int s = g_rowptr[warp];
    int e = g_rowptr[warp + 1];

    const char* S1b = (const char*)g_s1h + (size_t)lane * 8;   // row stride 256B
    unsigned long long a01 = 0ull, a23 = 0ull;

    int i = s;
    if ((i & 1) && i < e) {
        int   c = __ldcs(&acol[i]);
        float v = __ldcs(&aval[i]);
        unsigned long long w = ldg64cg(S1b + (size_t)c * 256);
        unsigned long long vv = dup2(v);
        a01 = ffma2(vv, packf2(unpackf16((uint32_t)w)), a01);
        a23 = ffma2(vv, packf2(unpackf16((uint32_t)(w >> 32))), a23);
        i++;
    }
    for (; i + 1 < e; i += 2) {
        int2   c2 = __ldcs((const int2*)&acol[i]);
        float2 v2 = __ldcs((const float2*)&aval[i]);
        unsigned long long w0 = ldg64cg(S1b + (size_t)c2.x * 256);
        unsigned long long w1 = ldg64cg(S1b + (size_t)c2.y * 256);
        unsigned long long vx = dup2(v2.x), vy = dup2(v2.y);
        a01 = ffma2(vx, packf2(unpackf16((uint32_t)w0)), a01);
        a23 = ffma2(vx, packf2(unpackf16((uint32_t)(w0 >> 32))), a23);
        a01 = ffma2(vy, packf2(unpackf16((uint32_t)w1)), a01);
        a23 = ffma2(vy, packf2(unpackf16((uint32_t)(w1 >> 32))), a23);
    }
    if (i < e) {
        int   c = __ldcs(&acol[i]);
        float v = __ldcs(&aval[i]);
        unsigned long long w = ldg64cg(S1b + (size_t)c * 256);
        unsigned long long vv = dup2(v);
        a01 = ffma2(vv, packf2(unpackf16((uint32_t)w)), a01);
        a23 = ffma2(vv, packf2(unpackf16((uint32_t)(w >> 32))), a23);
    }

    float2 p01 = unpack2(a01), p23 = unpack2(a23);
    float4 b = ((const float4*)b1)[lane];
    float4 r;
    r.x = fmaxf(p01.x + b.x, 0.f);
    r.y = fmaxf(p01.y + b.y, 0.f);
    r.z = fmaxf(p23.x + b.z, 0.f);
    r.w = fmaxf(p23.y + b.w, 0.f);
    uint2 pv;
    pv.x = packf16(make_float2(r.x, r.y));
    pv.y = packf16(make_float2(r.z, r.w));
    *(uint2*)((char*)g_hh + (size_t)warp * 256 + lane * 8) = pv;
}

// ---------------- GEMM2: s2 = h @ W2 (fp16 h stream, BM=256, BK=8, 2-stage) ----------------
#define G2_BM 256
#define G2_BK 8
#define G2_NT (NHID / G2_BK)     // 16
__global__ void __launch_bounds__(256) gemm2_kernel(const float* __restrict__ W2) {
    __shared__ uint32_t Hs[2][G2_BM * 4];     // 2 stages x 256 rows x 8 fp16 (4KB each)
    __shared__ float2   Wp[NHID * 20];        // 20 KB

    const int tid = threadIdx.x;
    const int pg  = tid & 3;
    const int rg  = tid >> 2;
    const int row0 = blockIdx.x * G2_BM;

    for (int j = tid; j < NHID * 20; j += 256) {
        int k = j / 20, p = j % 20;
        Wp[j] = *(const float2*)&W2[k * NCLASS + 2 * p];
    }

    unsigned hsb = (unsigned)__cvta_generic_to_shared(&Hs[0][0]);

    // per stage: 256 rows x 16B -> exactly 1 cpa16/thread (thread = row)
#define G2_PREFETCH(stage, k0)                                                     \
    do {                                                                           \
        int grow = row0 + tid;                                                     \
        cpa16(hsb + (stage) * 4096 + tid * 16,                                     \
              (const char*)g_hh + (size_t)grow * 256 + (k0) * 2, grow < NN);       \
        cpa_commit();                                                              \
    } while (0)

    G2_PREFETCH(0, 0);

    unsigned long long acc[4][5];
#pragma unroll
    for (int i = 0; i < 4; i++)
#pragma unroll
        for (int j = 0; j < 5; j++) acc[i][j] = 0ull;

    for (int t = 0; t < G2_NT; t++) {
        if (t + 1 < G2_NT) {
            G2_PREFETCH((t + 1) & 1, (t + 1) * G2_BK);
            cpa_wait1();
        } else {
            cpa_wait0();
        }
        __syncthreads();

        const int st = t & 1;
        const int kbase = t * G2_BK;
#pragma unroll
        for (int kp = 0; kp < 4; kp++) {          // kk = 2*kp, 2*kp+1
            float2 hf[4];
#pragma unroll
            for (int i = 0; i < 4; i++)
                hf[i] = unpackf16(Hs[st][(rg + 64 * i) * 4 + kp]);
#pragma unroll
            for (int half = 0; half < 2; half++) {
                int kk = kbase + 2 * kp + half;
                unsigned long long wv[5];
#pragma unroll
                for (int j = 0; j < 5; j++)
                    wv[j] = *(const unsigned long long*)&Wp[kk * 20 + pg * 5 + j];
                unsigned long long hd[4];
#pragma unroll
                for (int i = 0; i < 4; i++)
                    hd[i] = dup2(half ? hf[i].y : hf[i].x);
#pragma unroll
                for (int i = 0; i < 4; i++)
#pragma unroll
                    for (int j = 0; j < 5; j++)
                        acc[i][j] = ffma2(hd[i], wv[j], acc[i][j]);
            }
        }
        __syncthreads();
    }

#pragma unroll
    for (int i = 0; i < 4; i++) {
        int grow = row0 + rg + 64 * i;
        if (grow < NN) {
#pragma unroll
            for (int j = 0; j < 5; j++) {
                float2 v = unpack2(acc[i][j]);
                *(float2*)&g_s2[(size_t)grow * NCLASS + 2 * (pg * 5 + j)] = v;
            }
        }
    }
#undef G2_PREFETCH
}

// ---------------- SpMM2 + bias + log_softmax (3 slots x 2-deep, lanes 0-29) ----------------
__global__ void spmm2_lsm_kernel(const int* __restrict__ acol, const float* __restrict__ aval,
                                 const float* __restrict__ b2, float* __restrict__ out) {
    int warp = (blockIdx.x * blockDim.x + threadIdx.x) >> 5;
    int lane = threadIdx.x & 31;
    if (warp >= NN) return;

    int s = g_rowptr[warp];
    int e = g_rowptr[warp + 1];

    const int slot = lane / 10;
    const int seg  = lane - slot * 10;
    const bool lact = lane < 30;

    const char* S2b = (const char*)g_s2 + (size_t)seg * 16;
    unsigned long long acc0 = 0ull, acc1 = 0ull;

    int i = s;
    for (; i + 5 < e; i += 6) {
        int ei0 = i + slot, ei1 = i + 3 + slot;
        int c0 = 0, c1 = 0;
        float v0 = 0.f, v1 = 0.f;
        unsigned long long d0a = 0ull, d1a = 0ull, d0b = 0ull, d1b = 0ull;
        if (lact) {
            c0 = __ldcs(&acol[ei0]);
            c1 = __ldcs(&acol[ei1]);
            v0 = __ldcs(&aval[ei0]);
            v1 = __ldcs(&aval[ei1]);
            ldg128cg(S2b + (size_t)c0 * 160, d0a, d1a);
            ldg128cg(S2b + (size_t)c1 * 160, d0b, d1b);
        }
        unsigned long long vv0 = dup2(v0), vv1 = dup2(v1);
        acc0 = ffma2(vv0, d0a, acc0);
        acc1 = ffma2(vv0, d1a, acc1);
        acc0 = ffma2(vv1, d0b, acc0);
        acc1 = ffma2(vv1, d1b, acc1);
    }
    for (; i < e; i += 3) {
        int ei = i + slot;
        bool ok = lact && (ei < e);
        int   c = 0;
        float v = 0.f;
        if (ok) {
            c = __ldcs(&acol[ei]);
            v = __ldcs(&aval[ei]);
        }
        unsigned long long d0 = 0ull, d1 = 0ull;
        if (ok) ldg128cg(S2b + (size_t)c * 160, d0, d1);
        unsigned long long vv = dup2(v);
        acc0 = ffma2(vv, d0, acc0);
        acc1 = ffma2(vv, d1, acc1);
    }

    float2 a0 = unpack2(acc0), a1 = unpack2(acc1);
    float vals[4] = {a0.x, a0.y, a1.x, a1.y};
#pragma unroll
    for (int j = 0; j < 4; j++) {
        float v10 = __shfl_down_sync(0xFFFFFFFFu, vals[j], 10);
        float v20 = __shfl_down_sync(0xFFFFFFFFu, vals[j], 20);
        vals[j] = vals[j] + v10 + v20;
    }

    bool outl = lane < 10;
    if (outl) {
        float4 bb = __ldg((const float4*)&b2[4 * seg]);
        vals[0] += bb.x; vals[1] += bb.y; vals[2] += bb.z; vals[3] += bb.w;
    }

    float m = outl ? fmaxf(fmaxf(vals[0], vals[1]), fmaxf(vals[2], vals[3])) : -INFINITY;
#pragma unroll
    for (int off = 16; off > 0; off >>= 1)
        m = fmaxf(m, __shfl_xor_sync(0xFFFFFFFFu, m, off));

    float se = outl ? (expf(vals[0] - m) + expf(vals[1] - m) +
                       expf(vals[2] - m) + expf(vals[3] - m)) : 0.f;
#pragma unroll
    for (int off = 16; off > 0; off >>= 1)
        se += __shfl_xor_sync(0xFFFFFFFFu, se, off);

    float lse = m + logf(se);
    if (outl) {
        float4 o;
        o.x = vals[0] - lse; o.y = vals[1] - lse;
        o.z = vals[2] - lse; o.w = vals[3] - lse;
        *(float4*)&out[(size_t)warp * NCLASS + 4 * seg] = o;
    }
}

// ---------------- launch ----------------
extern "C" void kernel_launch(void* const* d_in, const int* in_sizes, int n_in,
                              void* d_out, int out_size) {
    const float* x    = (const float*)d_in[0];
    const int*   arow = (const int*)  d_in[1];
    const int*   acol = (const int*)  d_in[2];
    const float* aval = (const float*)d_in[3];
    // d_in[4] = i (unused)
    const float* W1 = (const float*)d_in[5];
    const float* b1 = (const float*)d_in[6];
    const float* W2 = (const float*)d_in[7];
    const float* b2 = (const float*)d_in[8];
    float* out = (float*)d_out;

    build_rowptr_kernel<<<(NN + 1 + 255) / 256, 256>>>(arow);
    w1bf16_kernel<<<(NFEAT * NHID + 255) / 256, 256>>>(W1);
    gemm1_bf16_kernel<<<(NN + 127) / 128, 512>>>(x);
    spmm1_kernel<<<(NN * 32 + 255) / 256, 256>>>(acol, aval, b1);
    gemm2_kernel<<<(NN + G2_BM - 1) / G2_BM, 256>>>(W2);
    spmm2_lsm_kernel<<<(NN * 32 + 255) / 256, 256>>>(acol, aval, b2, out);
}